// round 13
// baseline (speedup 1.0000x reference)
#include <cuda_runtime.h>
#include <cstdint>

#define BB 2
#define SS 2048
#define DD 1024
#define HH 16
#define HD 64
#define MROWS (BB*SS)   // 4096
#define N_QKV (3*DD)    // 3072
#define KDIM 1024
#define NCHUNK (KDIM/32)

// ---------------- device scratch (no allocation allowed) -------------------
__device__ __align__(128) float g_xa[MROWS/128 * NCHUNK * 4096];  // A-frag of x
__device__ __align__(128) float g_ya[MROWS/128 * NCHUNK * 4096];  // A-frag of attn out
__device__ __align__(128) float g_wa[N_QKV/128 * NCHUNK * 4096];  // B-frag of w_attn
__device__ __align__(128) float g_wp[DD/128   * NCHUNK * 4096];   // B-frag of w_proj
__device__ __align__(128) float g_qf[32 * 131072];  // A-frag Q [bh][mb128][kb8][128]
__device__ __align__(128) float g_kf[32 * 131072];  // B-frag K [bh][sb256][kb8][64]
__device__ __align__(128) float g_vf[32 * 131072];  // B-frag V [bh][kt32][nb8][kb8][64]

__device__ __forceinline__ uint32_t f2tf(float x) {
    uint32_t r;
    asm("cvt.rna.tf32.f32 %0, %1;" : "=r"(r) : "f"(x));
    return r;
}
__device__ __forceinline__ float f2tff(float x) { return __uint_as_float(f2tf(x)); }

__device__ __forceinline__ uint32_t smem_u32(const void* p) {
    uint32_t a;
    asm("{ .reg .u64 t; cvta.to.shared.u64 t, %1; cvt.u32.u64 %0, t; }" : "=r"(a) : "l"(p));
    return a;
}

#define MMA_TF32(d, a, b) \
    asm volatile("mma.sync.aligned.m16n8k8.row.col.f32.tf32.tf32.f32 " \
        "{%0,%1,%2,%3}, {%4,%5,%6,%7}, {%8,%9}, {%0,%1,%2,%3};" \
        : "+f"((d)[0]), "+f"((d)[1]), "+f"((d)[2]), "+f"((d)[3]) \
        : "r"((a)[0]), "r"((a)[1]), "r"((a)[2]), "r"((a)[3]), \
          "r"((b)[0]), "r"((b)[1]))

#define CP16(dst, src) \
    asm volatile("cp.async.cg.shared.global [%0], [%1], 16;" :: "r"(dst), "l"(src) : "memory")
#define CP_COMMIT() asm volatile("cp.async.commit_group;" ::: "memory")
#define CP_WAIT1()  asm volatile("cp.async.wait_group 1;" ::: "memory")

// ---------------------------------------------------------------------------
// Direct fragment-layout scatter helpers (tf32 bits)
// ---------------------------------------------------------------------------
__device__ __forceinline__ void store_qkv_frag(int m, int n, float val) {
    const int b = m >> 11, s = m & 2047;
    const int which = n >> 10, h = (n >> 6) & 15, d = n & 63;
    const int bh = (b << 4) | h;
    const float tv = f2tff(val);
    if (which == 0) {
        int off = bh * 131072 + (s >> 4) * 1024 + (d >> 3) * 128
                + (((s & 7) << 2) | (d & 3)) * 4
                + ((s & 8) ? 1 : 0) + ((d & 4) ? 2 : 0);
        g_qf[off] = tv;
    } else if (which == 1) {
        int off = bh * 131072 + (s >> 3) * 512 + (d >> 3) * 64
                + (((s & 7) << 2) | (d & 3)) * 2 + ((d & 4) ? 1 : 0);
        g_kf[off] = tv;
    } else {
        int off = bh * 131072 + (s >> 6) * 4096 + (d >> 3) * 512 + ((s & 63) >> 3) * 64
                + (((d & 7) << 2) | (s & 3)) * 2 + ((s & 4) ? 1 : 0);
        g_vf[off] = tv;
    }
}

__device__ __forceinline__ void store_ya_frag(int m, int k, float val) {
    int off = (m >> 7) * 131072 + (k >> 5) * 4096 + ((m >> 4) & 7) * 512
            + ((k >> 3) & 3) * 128 + (((m & 7) << 2) | (k & 3)) * 4
            + ((m & 8) ? 1 : 0) + ((k & 4) ? 2 : 0);
    g_ya[off] = f2tff(val);
}

// ---------------------------------------------------------------------------
// Fused pre-conversion (one launch, block-range dispatch) — unchanged
// ---------------------------------------------------------------------------
__global__ __launch_bounds__(256) void conv_all(const float* __restrict__ X,
                                                const float* __restrict__ Wa,
                                                const float* __restrict__ Wp,
                                                float* __restrict__ xa,
                                                float* __restrict__ wa,
                                                float* __restrict__ wp) {
    int blk = blockIdx.x;
    if (blk < 4096) {
        int idx = blk * 256 + threadIdx.x;
        int lane = idx & 31;
        int kb = (idx >> 5) & 3;
        int mb = (idx >> 7) & 7;
        int chunk = (idx >> 10) & 31;
        int mtile = idx >> 15;
        int r = lane >> 2, c = lane & 3;
        int m = mtile * 128 + mb * 16;
        int k = chunk * 32 + kb * 8;
        float4 v;
        v.x = f2tff(X[(size_t)(m + r) * KDIM + k + c]);
        v.y = f2tff(X[(size_t)(m + r + 8) * KDIM + k + c]);
        v.z = f2tff(X[(size_t)(m + r) * KDIM + k + c + 4]);
        v.w = f2tff(X[(size_t)(m + r + 8) * KDIM + k + c + 4]);
        *(float4*)(xa + (size_t)idx * 4) = v;
    } else if (blk < 10240) {
        const int N = N_QKV;
        int idx = (blk - 4096) * 256 + threadIdx.x;
        int lane = idx & 31;
        int kb = (idx >> 5) & 3;
        int nb = (idx >> 7) & 15;
        int chunk = (idx >> 11) & 31;
        int ntile = idx >> 16;
        int n = ntile * 128 + nb * 8 + (lane >> 2);
        int k = chunk * 32 + kb * 8 + (lane & 3);
        float2 v;
        v.x = f2tff(Wa[(size_t)k * N + n]);
        v.y = f2tff(Wa[(size_t)(k + 4) * N + n]);
        *(float2*)(wa + (size_t)idx * 2) = v;
    } else {
        const int N = DD;
        int idx = (blk - 10240) * 256 + threadIdx.x;
        int lane = idx & 31;
        int kb = (idx >> 5) & 3;
        int nb = (idx >> 7) & 15;
        int chunk = (idx >> 11) & 31;
        int ntile = idx >> 16;
        int n = ntile * 128 + nb * 8 + (lane >> 2);
        int k = chunk * 32 + kb * 8 + (lane & 3);
        float2 v;
        v.x = f2tff(Wp[(size_t)k * N + n]);
        v.y = f2tff(Wp[(size_t)(k + 4) * N + n]);
        *(float2*)(wp + (size_t)idx * 2) = v;
    }
}

// ---------------------------------------------------------------------------
// GEMM (R8/R11 config, unchanged)
// ---------------------------------------------------------------------------
#define GEMM_SMEM (3 * 32768)

template<int N, bool QKV>
__global__ __launch_bounds__(256, 2) void gemm_cp(const float* __restrict__ Afrag,
                                                  const float* __restrict__ Bfrag,
                                                  const float* __restrict__ bias,
                                                  float* __restrict__ Cout) {
    extern __shared__ float sm[];
    const uint32_t sb = smem_u32(sm);
    const int t = threadIdx.x;
    const int wid = t >> 5, lane = t & 31;
    const int warp_m = wid & 3, warp_n = wid >> 2;
    const int m0 = blockIdx.y * 128;
    const int n0 = blockIdx.x * 128;

    const float* Atile = Afrag + (size_t)blockIdx.y * (NCHUNK * 4096);
    const float* Btile = Bfrag + (size_t)blockIdx.x * (NCHUNK * 4096);

    float acc[2][8][4];
#pragma unroll
    for (int i = 0; i < 2; i++)
#pragma unroll
        for (int j = 0; j < 8; j++)
#pragma unroll
            for (int r = 0; r < 4; r++) acc[i][j][r] = 0.f;

#define ISSUE(c, s) do { \
        const float4* As_ = (const float4*)(Atile + (size_t)(c) * 4096) + t; \
        const float4* Bs_ = (const float4*)(Btile + (size_t)(c) * 4096) + t; \
        uint32_t d_ = sb + (uint32_t)(s) * 32768u + (uint32_t)t * 16u; \
        _Pragma("unroll") \
        for (int q = 0; q < 4; q++) CP16(d_ + q * 4096u, As_ + q * 256); \
        _Pragma("unroll") \
        for (int q = 0; q < 4; q++) CP16(d_ + 16384u + q * 4096u, Bs_ + q * 256); \
    } while (0)

    ISSUE(0, 0); CP_COMMIT();
    ISSUE(1, 1); CP_COMMIT();

    int stage = 0;
    int istage = 2;
#pragma unroll 1
    for (int c = 0; c < NCHUNK; c++) {
        CP_WAIT1();
        __syncthreads();

        const float* Ab = sm + stage * 8192;
        const float* Bb = Ab + 4096;
#pragma unroll
        for (int kb = 0; kb < 4; kb++) {
            uint32_t af[2][4], bf[8][2];
#pragma unroll
            for (int i = 0; i < 2; i++) {
                float4 v = *(const float4*)(Ab + ((warp_m * 2 + i) * 4 + kb) * 128 + lane * 4);
                af[i][0] = __float_as_uint(v.x); af[i][1] = __float_as_uint(v.y);
                af[i][2] = __float_as_uint(v.z); af[i][3] = __float_as_uint(v.w);
            }
#pragma unroll
            for (int j = 0; j < 8; j++) {
                float2 v = *(const float2*)(Bb + ((warp_n * 8 + j) * 4 + kb) * 64 + lane * 2);
                bf[j][0] = __float_as_uint(v.x); bf[j][1] = __float_as_uint(v.y);
            }
#pragma unroll
            for (int i = 0; i < 2; i++)
#pragma unroll
                for (int j = 0; j < 8; j++)
                    MMA_TF32(acc[i][j], af[i], bf[j]);
        }
        if (c + 2 < NCHUNK) ISSUE(c + 2, istage);
        CP_COMMIT();
        stage = (stage == 2) ? 0 : stage + 1;
        istage = (istage == 2) ? 0 : istage + 1;
    }
#undef ISSUE

    const int r0 = lane >> 2;
    const int cp = (lane & 3) * 2;
#pragma unroll
    for (int i = 0; i < 2; i++) {
        const int mbase = m0 + warp_m * 32 + i * 16;
        const int m1 = mbase + r0;
        const int m2 = m1 + 8;
#pragma unroll
        for (int j = 0; j < 8; j++) {
            const int n = n0 + warp_n * 64 + j * 8 + cp;
            const float bx = bias[n], by = bias[n + 1];
            if (QKV) {
                store_qkv_frag(m1, n,     acc[i][j][0] + bx);
                store_qkv_frag(m1, n + 1, acc[i][j][1] + by);
                store_qkv_frag(m2, n,     acc[i][j][2] + bx);
                store_qkv_frag(m2, n + 1, acc[i][j][3] + by);
            } else {
                *(float2*)(Cout + (size_t)m1 * DD + n) =
                    make_float2(acc[i][j][0] + bx, acc[i][j][1] + by);
                *(float2*)(Cout + (size_t)m2 * DD + n) =
                    make_float2(acc[i][j][2] + bx, acc[i][j][3] + by);
            }
        }
    }
}

// ---------------------------------------------------------------------------
// Flash attention v5: 128 threads (4 warps x 32 q-rows).
// - block0 softmax+transpose+PV issued BEFORE block1 softmax (pipe overlap)
// - exp2f with folded scale (shorter softmax chain)
// - jlim: skip fully-masked key-blocks on diagonal tiles
// ---------------------------------------------------------------------------
#define ATT2_SMEM (3 * 32768)
#define SCL2 0.1803368801111244f   // 0.125 * log2(e)

__global__ __launch_bounds__(128, 2) void attn_mma2() {
    extern __shared__ float sh[];
    const uint32_t sbase = smem_u32(sh);
    const int t = threadIdx.x;
    const int w = t >> 5, l = t & 31;
    const int qt = gridDim.x - 1 - blockIdx.x;   // heavy tiles first
    const int bh = blockIdx.y;

    const float* Qf  = g_qf + (size_t)bh * 131072 + (size_t)(qt * 8 + w * 2) * 1024;
    const float* Kbh = g_kf + (size_t)bh * 131072;
    const float* Vbh = g_vf + (size_t)bh * 131072;

    uint32_t qa0[8][4], qa1[8][4];
#pragma unroll
    for (int kb = 0; kb < 8; kb++) {
        float4 v0 = *(const float4*)(Qf + kb * 128 + l * 4);
        float4 v1 = *(const float4*)(Qf + 1024 + kb * 128 + l * 4);
        qa0[kb][0] = __float_as_uint(v0.x); qa0[kb][1] = __float_as_uint(v0.y);
        qa0[kb][2] = __float_as_uint(v0.z); qa0[kb][3] = __float_as_uint(v0.w);
        qa1[kb][0] = __float_as_uint(v1.x); qa1[kb][1] = __float_as_uint(v1.y);
        qa1[kb][2] = __float_as_uint(v1.z); qa1[kb][3] = __float_as_uint(v1.w);
    }

    float O0[8][4], O1[8][4];
#pragma unroll
    for (int j = 0; j < 8; j++)
#pragma unroll
        for (int r = 0; r < 4; r++) { O0[j][r] = 0.f; O1[j][r] = 0.f; }
    float m01 = -1e30f, m02 = -1e30f, l01 = 0.f, l02 = 0.f;
    float m11 = -1e30f, m12 = -1e30f, l11 = 0.f, l12 = 0.f;

    const int ntiles = 2 * qt + 2;
    const int qrow_lo = qt * 128 + w * 32;
    const int qr1 = qrow_lo + (l >> 2);
    const int qr2 = qr1 + 8;
    const int qr3 = qr1 + 16;
    const int qr4 = qr1 + 24;

    const unsigned FULL = 0xffffffffu;
    const int sgrp = l & 0x1c;
    const int src0 = sgrp + ((l & 3) >> 1);
    const int src2 = src0 + 2;
    const bool oddl = (l & 1);

#define AISSUE(kt) do { \
        if ((kt) < ntiles) { \
            const float4* ks_ = (const float4*)(Kbh + (size_t)(kt) * 4096) + t; \
            const float4* vs_ = (const float4*)(Vbh + (size_t)(kt) * 4096) + t; \
            uint32_t db_ = sbase + (uint32_t)((kt) % 3) * 32768u + (uint32_t)t * 16u; \
            _Pragma("unroll") \
            for (int q = 0; q < 8; q++) CP16(db_ + q * 2048u, ks_ + q * 128); \
            _Pragma("unroll") \
            for (int q = 0; q < 8; q++) CP16(db_ + 16384u + q * 2048u, vs_ + q * 128); \
        } } while (0)

// transpose one S block (C-frag) into A-frag registers via quad shuffles
#define TRANSPOSE_P(Sarr, paarr) do { \
    _Pragma("unroll") \
    for (int j = 0; j < 8; j++) { \
        float t0 = f2tff((Sarr)[j][0]), t1 = f2tff((Sarr)[j][1]); \
        float t2 = f2tff((Sarr)[j][2]), t3 = f2tff((Sarr)[j][3]); \
        float a0v0 = __shfl_sync(FULL, t0, src0); \
        float a0v1 = __shfl_sync(FULL, t1, src0); \
        float a1v0 = __shfl_sync(FULL, t2, src0); \
        float a1v1 = __shfl_sync(FULL, t3, src0); \
        float a2v0 = __shfl_sync(FULL, t0, src2); \
        float a2v1 = __shfl_sync(FULL, t1, src2); \
        float a3v0 = __shfl_sync(FULL, t2, src2); \
        float a3v1 = __shfl_sync(FULL, t3, src2); \
        (paarr)[j][0] = __float_as_uint(oddl ? a0v1 : a0v0); \
        (paarr)[j][1] = __float_as_uint(oddl ? a1v1 : a1v0); \
        (paarr)[j][2] = __float_as_uint(oddl ? a2v1 : a2v0); \
        (paarr)[j][3] = __float_as_uint(oddl ? a3v1 : a3v0); \
    } } while (0)

    AISSUE(0); CP_COMMIT();
    AISSUE(1); CP_COMMIT();

    int stage = 0;
#pragma unroll 1
    for (int kt = 0; kt < ntiles; kt++) {
        CP_WAIT1();
        __syncthreads();
        AISSUE(kt + 2);
        CP_COMMIT();

        const bool active = (kt * 64) <= (qrow_lo + 31);
        if (active) {
            const float* Kb = sh + stage * 8192;
            const float* Vb = Kb + 4096;

            const bool diag = (kt * 64 + 63) > qrow_lo;
            const int jlim = diag ? ((qrow_lo + 31 - kt * 64) >> 3) : 7;

            // ---- S = Q @ K^T (skip fully-masked key blocks) ----
            float S0[8][4], S1[8][4];
#pragma unroll
            for (int j = 0; j < 8; j++) {
                if (j <= jlim) {
#pragma unroll
                    for (int r = 0; r < 4; r++) { S0[j][r] = 0.f; S1[j][r] = 0.f; }
#pragma unroll
                    for (int kb = 0; kb < 8; kb++) {
                        float2 bv = *(const float2*)&Kb[(j * 8 + kb) * 64 + l * 2];
                        uint32_t bf[2] = {__float_as_uint(bv.x), __float_as_uint(bv.y)};
                        MMA_TF32(S0[j], qa0[kb], bf);
                        MMA_TF32(S1[j], qa1[kb], bf);
                    }
                } else {
#pragma unroll
                    for (int r = 0; r < 4; r++) { S0[j][r] = -1e30f; S1[j][r] = -1e30f; }
                }
            }

            // ---- scale (folded log2e) + causal mask ----
            if (diag) {
#pragma unroll
                for (int j = 0; j < 8; j++) {
                    int c0 = kt * 64 + j * 8 + (l & 3) * 2, c1 = c0 + 1;
                    S0[j][0] = (c0 <= qr1) ? S0[j][0] * SCL2 : -1e30f;
                    S0[j][1] = (c1 <= qr1) ? S0[j][1] * SCL2 : -1e30f;
                    S0[j][2] = (c0 <= qr2) ? S0[j][2] * SCL2 : -1e30f;
                    S0[j][3] = (c1 <= qr2) ? S0[j][3] * SCL2 : -1e30f;
                    S1[j][0] = (c0 <= qr3) ? S1[j][0] * SCL2 : -1e30f;
                    S1[j][1] = (c1 <= qr3) ? S1[j][1] * SCL2 : -1e30f;
                    S1[j][2] = (c0 <= qr4) ? S1[j][2] * SCL2 : -1e30f;
                    S1[j][3] = (c1 <= qr4) ? S1[j][3] * SCL2 : -1e30f;
                }
            } else {
#pragma unroll
                for (int j = 0; j < 8; j++)
#pragma unroll
                    for (int r = 0; r < 4; r++) { S0[j][r] *= SCL2; S1[j][r] *= SCL2; }
            }

            // ================= block 0: softmax -> transpose -> PV =========
            {
                float rm1 = -1e30f, rm2 = -1e30f;
#pragma unroll
                for (int j = 0; j < 8; j++) {
                    rm1 = fmaxf(rm1, fmaxf(S0[j][0], S0[j][1]));
                    rm2 = fmaxf(rm2, fmaxf(S0[j][2], S0[j][3]));
                }
                rm1 = fmaxf(rm1, __shfl_xor_sync(FULL, rm1, 1));
                rm1 = fmaxf(rm1, __shfl_xor_sync(FULL, rm1, 2));
                rm2 = fmaxf(rm2, __shfl_xor_sync(FULL, rm2, 1));
                rm2 = fmaxf(rm2, __shfl_xor_sync(FULL, rm2, 2));
                float mn1 = fmaxf(m01, rm1), mn2 = fmaxf(m02, rm2);
                float fi1 = exp2f(m01 - mn1), fi2 = exp2f(m02 - mn2);
                m01 = mn1; m02 = mn2;
                float rs1 = 0.f, rs2 = 0.f;
#pragma unroll
                for (int j = 0; j < 8; j++) {
                    S0[j][0] = exp2f(S0[j][0] - m01);
                    S0[j][1] = exp2f(S0[j][1] - m01);
                    S0[j][2] = exp2f(S0[j][2] - m02);
                    S0[j][3] = exp2f(S0[j][3] - m02);
                    rs1 += S0[j][0] + S0[j][1];
                    rs2 += S0[j][2] + S0[j][3];
                }
                rs1 += __shfl_xor_sync(FULL, rs1, 1);
                rs1 += __shfl_xor_sync(FULL, rs1, 2);
                rs2 += __shfl_xor_sync(FULL, rs2, 1);
                rs2 += __shfl_xor_sync(FULL, rs2, 2);
                l01 = l01 * fi1 + rs1;
                l02 = l02 * fi2 + rs2;
#pragma unroll
                for (int j = 0; j < 8; j++) {
                    O0[j][0] *= fi1; O0[j][1] *= fi1;
                    O0[j][2] *= fi2; O0[j][3] *= fi2;
                }

                uint32_t pa0[8][4];
                TRANSPOSE_P(S0, pa0);
                // PV0 — issues while block1 softmax executes next
#pragma unroll
                for (int j = 0; j < 8; j++)
#pragma unroll
                    for (int kb = 0; kb < 8; kb++)
                        if (kb <= jlim) {
                            float2 bv = *(const float2*)&Vb[(j * 8 + kb) * 64 + l * 2];
                            uint32_t bf[2] = {__float_as_uint(bv.x), __float_as_uint(bv.y)};
                            MMA_TF32(O0[j], pa0[kb], bf);
                        }
            }

            // ================= block 1: softmax -> transpose -> PV =========
            {
                float rm1 = -1e30f, rm2 = -1e30f;
#pragma unroll
                for (int j = 0; j < 8; j++) {
                    rm1 = fmaxf(rm1, fmaxf(S1[j][0], S1[j][1]));
                    rm2 = fmaxf(rm2, fmaxf(S1[j][2], S1[j][3]));
                }
                rm1 = fmaxf(rm1, __shfl_xor_sync(FULL, rm1, 1));
                rm1 = fmaxf(rm1, __shfl_xor_sync(FULL, rm1, 2));
                rm2 = fmaxf(rm2, __shfl_xor_sync(FULL, rm2, 1));
                rm2 = fmaxf(rm2, __shfl_xor_sync(FULL, rm2, 2));
                float mn1 = fmaxf(m11, rm1), mn2 = fmaxf(m12, rm2);
                float fi1 = exp2f(m11 - mn1), fi2 = exp2f(m12 - mn2);
                m11 = mn1; m12 = mn2;
                float rs1 = 0.f, rs2 = 0.f;
#pragma unroll
                for (int j = 0; j < 8; j++) {
                    S1[j][0] = exp2f(S1[j][0] - m11);
                    S1[j][1] = exp2f(S1[j][1] - m11);
                    S1[j][2] = exp2f(S1[j][2] - m12);
                    S1[j][3] = exp2f(S1[j][3] - m12);
                    rs1 += S1[j][0] + S1[j][1];
                    rs2 += S1[j][2] + S1[j][3];
                }
                rs1 += __shfl_xor_sync(FULL, rs1, 1);
                rs1 += __shfl_xor_sync(FULL, rs1, 2);
                rs2 += __shfl_xor_sync(FULL, rs2, 1);
                rs2 += __shfl_xor_sync(FULL, rs2, 2);
                l11 = l11 * fi1 + rs1;
                l12 = l12 * fi2 + rs2;
#pragma unroll
                for (int j = 0; j < 8; j++) {
                    O1[j][0] *= fi1; O1[j][1] *= fi1;
                    O1[j][2] *= fi2; O1[j][3] *= fi2;
                }

                uint32_t pa1[8][4];
                TRANSPOSE_P(S1, pa1);
#pragma unroll
                for (int j = 0; j < 8; j++)
#pragma unroll
                    for (int kb = 0; kb < 8; kb++)
                        if (kb <= jlim) {
                            float2 bv = *(const float2*)&Vb[(j * 8 + kb) * 64 + l * 2];
                            uint32_t bf[2] = {__float_as_uint(bv.x), __float_as_uint(bv.y)};
                            MMA_TF32(O1[j], pa1[kb], bf);
                        }
            }
        }

        stage = (stage == 2) ? 0 : stage + 1;
    }
#undef AISSUE
#undef TRANSPOSE_P

    // ---- epilogue ----
    const int b = bh >> 4, h = bh & 15;
    const float i01 = 1.f / l01, i02 = 1.f / l02;
    const float i11 = 1.f / l11, i12 = 1.f / l12;
    const int mgA = b * SS + qr1;
    const int mgB = b * SS + qr2;
    const int mgC = b * SS + qr3;
    const int mgD = b * SS + qr4;
#pragma unroll
    for (int j = 0; j < 8; j++) {
        int c0 = j * 8 + (l & 3) * 2;
        int k = h * HD + c0;
        store_ya_frag(mgA, k,     O0[j][0] * i01);
        store_ya_frag(mgA, k + 1, O0[j][1] * i01);
        store_ya_frag(mgB, k,     O0[j][2] * i02);
        store_ya_frag(mgB, k + 1, O0[j][3] * i02);
        store_ya_frag(mgC, k,     O1[j][0] * i11);
        store_ya_frag(mgC, k + 1, O1[j][1] * i11);
        store_ya_frag(mgD, k,     O1[j][2] * i12);
        store_ya_frag(mgD, k + 1, O1[j][3] * i12);
    }
}

// ---------------------------------------------------------------------------

extern "C" void kernel_launch(void* const* d_in, const int* in_sizes, int n_in,
                              void* d_out, int out_size) {
    const float* x      = (const float*)d_in[0];
    const float* w_attn = (const float*)d_in[1];
    const float* b_attn = (const float*)d_in[2];
    const float* w_proj = (const float*)d_in[3];
    const float* b_proj = (const float*)d_in[4];
    float* out = (float*)d_out;

    float* xa; cudaGetSymbolAddress((void**)&xa, g_xa);
    float* ya; cudaGetSymbolAddress((void**)&ya, g_ya);
    float* wa; cudaGetSymbolAddress((void**)&wa, g_wa);
    float* wp; cudaGetSymbolAddress((void**)&wp, g_wp);

    cudaFuncSetAttribute(gemm_cp<N_QKV, true>,
                         cudaFuncAttributeMaxDynamicSharedMemorySize, GEMM_SMEM);
    cudaFuncSetAttribute(gemm_cp<DD, false>,
                         cudaFuncAttributeMaxDynamicSharedMemorySize, GEMM_SMEM);
    cudaFuncSetAttribute(attn_mma2,
                         cudaFuncAttributeMaxDynamicSharedMemorySize, ATT2_SMEM);

    // 0) preconvert x + both weights in ONE launch
    conv_all<<<12288, 256>>>(x, w_attn, w_proj, xa, wa, wp);

    // 1) QKV projection -> frag buffers
    gemm_cp<N_QKV, true><<<dim3(N_QKV / 128, MROWS / 128), 256, GEMM_SMEM>>>(
        xa, wa, b_attn, nullptr);

    // 2) causal flash attention (v5) -> A-frag of y
    attn_mma2<<<dim3(SS / 128, BB * HH), 128, ATT2_SMEM>>>();

    // 3) output projection
    gemm_cp<DD, false><<<dim3(DD / 128, MROWS / 128), 256, GEMM_SMEM>>>(
        ya, wp, b_proj, out);
}

// round 14
// speedup vs baseline: 1.2885x; 1.2885x over previous
#include <cuda_runtime.h>
#include <cstdint>

#define BB 2
#define SS 2048
#define DD 1024
#define HH 16
#define HD 64
#define MROWS (BB*SS)   // 4096
#define N_QKV (3*DD)    // 3072
#define KDIM 1024
#define NCHUNK (KDIM/32)

// ---------------- device scratch (no allocation allowed) -------------------
__device__ __align__(128) float g_xa[MROWS/128 * NCHUNK * 4096];  // A-frag of x
__device__ __align__(128) float g_ya[MROWS/128 * NCHUNK * 4096];  // A-frag of attn out
__device__ __align__(128) float g_wa[N_QKV/128 * NCHUNK * 4096];  // B-frag of w_attn
__device__ __align__(128) float g_wp[DD/128   * NCHUNK * 4096];   // B-frag of w_proj
__device__ __align__(128) float g_qf[32 * 131072];  // A-frag Q [bh][mb128][kb8][128]
__device__ __align__(128) float g_kf[32 * 131072];  // B-frag K [bh][sb256][kb8][64]
__device__ __align__(128) float g_vf[32 * 131072];  // B-frag V [bh][kt32][nb8][kb8][64]

__device__ __forceinline__ uint32_t f2tf(float x) {
    uint32_t r;
    asm("cvt.rna.tf32.f32 %0, %1;" : "=r"(r) : "f"(x));
    return r;
}
__device__ __forceinline__ float f2tff(float x) { return __uint_as_float(f2tf(x)); }

__device__ __forceinline__ uint32_t smem_u32(const void* p) {
    uint32_t a;
    asm("{ .reg .u64 t; cvta.to.shared.u64 t, %1; cvt.u32.u64 %0, t; }" : "=r"(a) : "l"(p));
    return a;
}

#define MMA_TF32(d, a, b) \
    asm volatile("mma.sync.aligned.m16n8k8.row.col.f32.tf32.tf32.f32 " \
        "{%0,%1,%2,%3}, {%4,%5,%6,%7}, {%8,%9}, {%0,%1,%2,%3};" \
        : "+f"((d)[0]), "+f"((d)[1]), "+f"((d)[2]), "+f"((d)[3]) \
        : "r"((a)[0]), "r"((a)[1]), "r"((a)[2]), "r"((a)[3]), \
          "r"((b)[0]), "r"((b)[1]))

#define CP16(dst, src) \
    asm volatile("cp.async.cg.shared.global [%0], [%1], 16;" :: "r"(dst), "l"(src) : "memory")
#define CP_COMMIT() asm volatile("cp.async.commit_group;" ::: "memory")
#define CP_WAIT1()  asm volatile("cp.async.wait_group 1;" ::: "memory")

// ---------------------------------------------------------------------------
// Direct fragment-layout scatter helpers (tf32 bits)
// ---------------------------------------------------------------------------
__device__ __forceinline__ void store_qkv_frag(int m, int n, float val) {
    const int b = m >> 11, s = m & 2047;
    const int which = n >> 10, h = (n >> 6) & 15, d = n & 63;
    const int bh = (b << 4) | h;
    const float tv = f2tff(val);
    if (which == 0) {
        int off = bh * 131072 + (s >> 4) * 1024 + (d >> 3) * 128
                + (((s & 7) << 2) | (d & 3)) * 4
                + ((s & 8) ? 1 : 0) + ((d & 4) ? 2 : 0);
        g_qf[off] = tv;
    } else if (which == 1) {
        int off = bh * 131072 + (s >> 3) * 512 + (d >> 3) * 64
                + (((s & 7) << 2) | (d & 3)) * 2 + ((d & 4) ? 1 : 0);
        g_kf[off] = tv;
    } else {
        int off = bh * 131072 + (s >> 6) * 4096 + (d >> 3) * 512 + ((s & 63) >> 3) * 64
                + (((d & 7) << 2) | (s & 3)) * 2 + ((s & 4) ? 1 : 0);
        g_vf[off] = tv;
    }
}

__device__ __forceinline__ void store_ya_frag(int m, int k, float val) {
    int off = (m >> 7) * 131072 + (k >> 5) * 4096 + ((m >> 4) & 7) * 512
            + ((k >> 3) & 3) * 128 + (((m & 7) << 2) | (k & 3)) * 4
            + ((m & 8) ? 1 : 0) + ((k & 4) ? 2 : 0);
    g_ya[off] = f2tff(val);
}

// ---------------------------------------------------------------------------
// Fused pre-conversion (one launch, block-range dispatch)
// ---------------------------------------------------------------------------
__global__ __launch_bounds__(256) void conv_all(const float* __restrict__ X,
                                                const float* __restrict__ Wa,
                                                const float* __restrict__ Wp,
                                                float* __restrict__ xa,
                                                float* __restrict__ wa,
                                                float* __restrict__ wp) {
    int blk = blockIdx.x;
    if (blk < 4096) {
        int idx = blk * 256 + threadIdx.x;
        int lane = idx & 31;
        int kb = (idx >> 5) & 3;
        int mb = (idx >> 7) & 7;
        int chunk = (idx >> 10) & 31;
        int mtile = idx >> 15;
        int r = lane >> 2, c = lane & 3;
        int m = mtile * 128 + mb * 16;
        int k = chunk * 32 + kb * 8;
        float4 v;
        v.x = f2tff(X[(size_t)(m + r) * KDIM + k + c]);
        v.y = f2tff(X[(size_t)(m + r + 8) * KDIM + k + c]);
        v.z = f2tff(X[(size_t)(m + r) * KDIM + k + c + 4]);
        v.w = f2tff(X[(size_t)(m + r + 8) * KDIM + k + c + 4]);
        *(float4*)(xa + (size_t)idx * 4) = v;
    } else if (blk < 10240) {
        const int N = N_QKV;
        int idx = (blk - 4096) * 256 + threadIdx.x;
        int lane = idx & 31;
        int kb = (idx >> 5) & 3;
        int nb = (idx >> 7) & 15;
        int chunk = (idx >> 11) & 31;
        int ntile = idx >> 16;
        int n = ntile * 128 + nb * 8 + (lane >> 2);
        int k = chunk * 32 + kb * 8 + (lane & 3);
        float2 v;
        v.x = f2tff(Wa[(size_t)k * N + n]);
        v.y = f2tff(Wa[(size_t)(k + 4) * N + n]);
        *(float2*)(wa + (size_t)idx * 2) = v;
    } else {
        const int N = DD;
        int idx = (blk - 10240) * 256 + threadIdx.x;
        int lane = idx & 31;
        int kb = (idx >> 5) & 3;
        int nb = (idx >> 7) & 15;
        int chunk = (idx >> 11) & 31;
        int ntile = idx >> 16;
        int n = ntile * 128 + nb * 8 + (lane >> 2);
        int k = chunk * 32 + kb * 8 + (lane & 3);
        float2 v;
        v.x = f2tff(Wp[(size_t)k * N + n]);
        v.y = f2tff(Wp[(size_t)(k + 4) * N + n]);
        *(float2*)(wp + (size_t)idx * 2) = v;
    }
}

// ---------------------------------------------------------------------------
// GEMM (R8/R11 config, unchanged)
// ---------------------------------------------------------------------------
#define GEMM_SMEM (3 * 32768)

template<int N, bool QKV>
__global__ __launch_bounds__(256, 2) void gemm_cp(const float* __restrict__ Afrag,
                                                  const float* __restrict__ Bfrag,
                                                  const float* __restrict__ bias,
                                                  float* __restrict__ Cout) {
    extern __shared__ float sm[];
    const uint32_t sb = smem_u32(sm);
    const int t = threadIdx.x;
    const int wid = t >> 5, lane = t & 31;
    const int warp_m = wid & 3, warp_n = wid >> 2;
    const int m0 = blockIdx.y * 128;
    const int n0 = blockIdx.x * 128;

    const float* Atile = Afrag + (size_t)blockIdx.y * (NCHUNK * 4096);
    const float* Btile = Bfrag + (size_t)blockIdx.x * (NCHUNK * 4096);

    float acc[2][8][4];
#pragma unroll
    for (int i = 0; i < 2; i++)
#pragma unroll
        for (int j = 0; j < 8; j++)
#pragma unroll
            for (int r = 0; r < 4; r++) acc[i][j][r] = 0.f;

#define ISSUE(c, s) do { \
        const float4* As_ = (const float4*)(Atile + (size_t)(c) * 4096) + t; \
        const float4* Bs_ = (const float4*)(Btile + (size_t)(c) * 4096) + t; \
        uint32_t d_ = sb + (uint32_t)(s) * 32768u + (uint32_t)t * 16u; \
        _Pragma("unroll") \
        for (int q = 0; q < 4; q++) CP16(d_ + q * 4096u, As_ + q * 256); \
        _Pragma("unroll") \
        for (int q = 0; q < 4; q++) CP16(d_ + 16384u + q * 4096u, Bs_ + q * 256); \
    } while (0)

    ISSUE(0, 0); CP_COMMIT();
    ISSUE(1, 1); CP_COMMIT();

    int stage = 0;
    int istage = 2;
#pragma unroll 1
    for (int c = 0; c < NCHUNK; c++) {
        CP_WAIT1();
        __syncthreads();

        const float* Ab = sm + stage * 8192;
        const float* Bb = Ab + 4096;
#pragma unroll
        for (int kb = 0; kb < 4; kb++) {
            uint32_t af[2][4], bf[8][2];
#pragma unroll
            for (int i = 0; i < 2; i++) {
                float4 v = *(const float4*)(Ab + ((warp_m * 2 + i) * 4 + kb) * 128 + lane * 4);
                af[i][0] = __float_as_uint(v.x); af[i][1] = __float_as_uint(v.y);
                af[i][2] = __float_as_uint(v.z); af[i][3] = __float_as_uint(v.w);
            }
#pragma unroll
            for (int j = 0; j < 8; j++) {
                float2 v = *(const float2*)(Bb + ((warp_n * 8 + j) * 4 + kb) * 64 + lane * 2);
                bf[j][0] = __float_as_uint(v.x); bf[j][1] = __float_as_uint(v.y);
            }
#pragma unroll
            for (int i = 0; i < 2; i++)
#pragma unroll
                for (int j = 0; j < 8; j++)
                    MMA_TF32(acc[i][j], af[i], bf[j]);
        }
        if (c + 2 < NCHUNK) ISSUE(c + 2, istage);
        CP_COMMIT();
        stage = (stage == 2) ? 0 : stage + 1;
        istage = (istage == 2) ? 0 : istage + 1;
    }
#undef ISSUE

    const int r0 = lane >> 2;
    const int cp = (lane & 3) * 2;
#pragma unroll
    for (int i = 0; i < 2; i++) {
        const int mbase = m0 + warp_m * 32 + i * 16;
        const int m1 = mbase + r0;
        const int m2 = m1 + 8;
#pragma unroll
        for (int j = 0; j < 8; j++) {
            const int n = n0 + warp_n * 64 + j * 8 + cp;
            const float bx = bias[n], by = bias[n + 1];
            if (QKV) {
                store_qkv_frag(m1, n,     acc[i][j][0] + bx);
                store_qkv_frag(m1, n + 1, acc[i][j][1] + by);
                store_qkv_frag(m2, n,     acc[i][j][2] + bx);
                store_qkv_frag(m2, n + 1, acc[i][j][3] + by);
            } else {
                *(float2*)(Cout + (size_t)m1 * DD + n) =
                    make_float2(acc[i][j][0] + bx, acc[i][j][1] + by);
                *(float2*)(Cout + (size_t)m2 * DD + n) =
                    make_float2(acc[i][j][2] + bx, acc[i][j][3] + by);
            }
        }
    }
}

// ---------------------------------------------------------------------------
// Flash attention (R12 structure + exp2f folded scale ONLY).
// 128 threads (4 warps x 32 q-rows, 2 m-blocks); K/V fragments shared by
// both m-blocks; 3-buffer cp.async; shuffle P transpose.
// ---------------------------------------------------------------------------
#define ATT2_SMEM (3 * 32768)
#define SCL2 0.1803368801111244f   // 0.125 * log2(e)

__global__ __launch_bounds__(128, 2) void attn_mma2() {
    extern __shared__ float sh[];
    const uint32_t sbase = smem_u32(sh);
    const int t = threadIdx.x;
    const int w = t >> 5, l = t & 31;
    const int qt = gridDim.x - 1 - blockIdx.x;   // heavy tiles first
    const int bh = blockIdx.y;

    const float* Qf  = g_qf + (size_t)bh * 131072 + (size_t)(qt * 8 + w * 2) * 1024;
    const float* Kbh = g_kf + (size_t)bh * 131072;
    const float* Vbh = g_vf + (size_t)bh * 131072;

    uint32_t qa0[8][4], qa1[8][4];
#pragma unroll
    for (int kb = 0; kb < 8; kb++) {
        float4 v0 = *(const float4*)(Qf + kb * 128 + l * 4);
        float4 v1 = *(const float4*)(Qf + 1024 + kb * 128 + l * 4);
        qa0[kb][0] = __float_as_uint(v0.x); qa0[kb][1] = __float_as_uint(v0.y);
        qa0[kb][2] = __float_as_uint(v0.z); qa0[kb][3] = __float_as_uint(v0.w);
        qa1[kb][0] = __float_as_uint(v1.x); qa1[kb][1] = __float_as_uint(v1.y);
        qa1[kb][2] = __float_as_uint(v1.z); qa1[kb][3] = __float_as_uint(v1.w);
    }

    float O0[8][4], O1[8][4];
#pragma unroll
    for (int j = 0; j < 8; j++)
#pragma unroll
        for (int r = 0; r < 4; r++) { O0[j][r] = 0.f; O1[j][r] = 0.f; }
    float m01 = -1e30f, m02 = -1e30f, l01 = 0.f, l02 = 0.f;
    float m11 = -1e30f, m12 = -1e30f, l11 = 0.f, l12 = 0.f;

    const int ntiles = 2 * qt + 2;
    const int qrow_lo = qt * 128 + w * 32;
    const int qr1 = qrow_lo + (l >> 2);
    const int qr2 = qr1 + 8;
    const int qr3 = qr1 + 16;
    const int qr4 = qr1 + 24;

    const unsigned FULL = 0xffffffffu;
    const int sgrp = l & 0x1c;
    const int src0 = sgrp + ((l & 3) >> 1);
    const int src2 = src0 + 2;
    const bool oddl = (l & 1);

#define AISSUE(kt) do { \
        if ((kt) < ntiles) { \
            const float4* ks_ = (const float4*)(Kbh + (size_t)(kt) * 4096) + t; \
            const float4* vs_ = (const float4*)(Vbh + (size_t)(kt) * 4096) + t; \
            uint32_t db_ = sbase + (uint32_t)((kt) % 3) * 32768u + (uint32_t)t * 16u; \
            _Pragma("unroll") \
            for (int q = 0; q < 8; q++) CP16(db_ + q * 2048u, ks_ + q * 128); \
            _Pragma("unroll") \
            for (int q = 0; q < 8; q++) CP16(db_ + 16384u + q * 2048u, vs_ + q * 128); \
        } } while (0)

    AISSUE(0); CP_COMMIT();
    AISSUE(1); CP_COMMIT();

    int stage = 0;
#pragma unroll 1
    for (int kt = 0; kt < ntiles; kt++) {
        CP_WAIT1();
        __syncthreads();
        AISSUE(kt + 2);
        CP_COMMIT();

        const bool active = (kt * 64) <= (qrow_lo + 31);
        if (active) {
            const float* Kb = sh + stage * 8192;
            const float* Vb = Kb + 4096;

            // ---- S = Q @ K^T (both m-blocks share each K fragment) ----
            float S0[8][4], S1[8][4];
#pragma unroll
            for (int j = 0; j < 8; j++) {
#pragma unroll
                for (int r = 0; r < 4; r++) { S0[j][r] = 0.f; S1[j][r] = 0.f; }
#pragma unroll
                for (int kb = 0; kb < 8; kb++) {
                    float2 bv = *(const float2*)&Kb[(j * 8 + kb) * 64 + l * 2];
                    uint32_t bf[2] = {__float_as_uint(bv.x), __float_as_uint(bv.y)};
                    MMA_TF32(S0[j], qa0[kb], bf);
                    MMA_TF32(S1[j], qa1[kb], bf);
                }
            }

            // ---- scale (folded log2e) + causal mask ----
            if (kt * 64 + 63 > qrow_lo) {
#pragma unroll
                for (int j = 0; j < 8; j++) {
                    int c0 = kt * 64 + j * 8 + (l & 3) * 2, c1 = c0 + 1;
                    S0[j][0] = (c0 <= qr1) ? S0[j][0] * SCL2 : -1e30f;
                    S0[j][1] = (c1 <= qr1) ? S0[j][1] * SCL2 : -1e30f;
                    S0[j][2] = (c0 <= qr2) ? S0[j][2] * SCL2 : -1e30f;
                    S0[j][3] = (c1 <= qr2) ? S0[j][3] * SCL2 : -1e30f;
                    S1[j][0] = (c0 <= qr3) ? S1[j][0] * SCL2 : -1e30f;
                    S1[j][1] = (c1 <= qr3) ? S1[j][1] * SCL2 : -1e30f;
                    S1[j][2] = (c0 <= qr4) ? S1[j][2] * SCL2 : -1e30f;
                    S1[j][3] = (c1 <= qr4) ? S1[j][3] * SCL2 : -1e30f;
                }
            } else {
#pragma unroll
                for (int j = 0; j < 8; j++)
#pragma unroll
                    for (int r = 0; r < 4; r++) { S0[j][r] *= SCL2; S1[j][r] *= SCL2; }
            }

            // ---- online softmax, block 0 (exp2) ----
            {
                float rm1 = -1e30f, rm2 = -1e30f;
#pragma unroll
                for (int j = 0; j < 8; j++) {
                    rm1 = fmaxf(rm1, fmaxf(S0[j][0], S0[j][1]));
                    rm2 = fmaxf(rm2, fmaxf(S0[j][2], S0[j][3]));
                }
                rm1 = fmaxf(rm1, __shfl_xor_sync(FULL, rm1, 1));
                rm1 = fmaxf(rm1, __shfl_xor_sync(FULL, rm1, 2));
                rm2 = fmaxf(rm2, __shfl_xor_sync(FULL, rm2, 1));
                rm2 = fmaxf(rm2, __shfl_xor_sync(FULL, rm2, 2));
                float mn1 = fmaxf(m01, rm1), mn2 = fmaxf(m02, rm2);
                float fi1 = exp2f(m01 - mn1), fi2 = exp2f(m02 - mn2);
                m01 = mn1; m02 = mn2;
                float rs1 = 0.f, rs2 = 0.f;
#pragma unroll
                for (int j = 0; j < 8; j++) {
                    S0[j][0] = exp2f(S0[j][0] - m01);
                    S0[j][1] = exp2f(S0[j][1] - m01);
                    S0[j][2] = exp2f(S0[j][2] - m02);
                    S0[j][3] = exp2f(S0[j][3] - m02);
                    rs1 += S0[j][0] + S0[j][1];
                    rs2 += S0[j][2] + S0[j][3];
                }
                rs1 += __shfl_xor_sync(FULL, rs1, 1);
                rs1 += __shfl_xor_sync(FULL, rs1, 2);
                rs2 += __shfl_xor_sync(FULL, rs2, 1);
                rs2 += __shfl_xor_sync(FULL, rs2, 2);
                l01 = l01 * fi1 + rs1;
                l02 = l02 * fi2 + rs2;
#pragma unroll
                for (int j = 0; j < 8; j++) {
                    O0[j][0] *= fi1; O0[j][1] *= fi1;
                    O0[j][2] *= fi2; O0[j][3] *= fi2;
                }
            }
            // ---- online softmax, block 1 (exp2) ----
            {
                float rm1 = -1e30f, rm2 = -1e30f;
#pragma unroll
                for (int j = 0; j < 8; j++) {
                    rm1 = fmaxf(rm1, fmaxf(S1[j][0], S1[j][1]));
                    rm2 = fmaxf(rm2, fmaxf(S1[j][2], S1[j][3]));
                }
                rm1 = fmaxf(rm1, __shfl_xor_sync(FULL, rm1, 1));
                rm1 = fmaxf(rm1, __shfl_xor_sync(FULL, rm1, 2));
                rm2 = fmaxf(rm2, __shfl_xor_sync(FULL, rm2, 1));
                rm2 = fmaxf(rm2, __shfl_xor_sync(FULL, rm2, 2));
                float mn1 = fmaxf(m11, rm1), mn2 = fmaxf(m12, rm2);
                float fi1 = exp2f(m11 - mn1), fi2 = exp2f(m12 - mn2);
                m11 = mn1; m12 = mn2;
                float rs1 = 0.f, rs2 = 0.f;
#pragma unroll
                for (int j = 0; j < 8; j++) {
                    S1[j][0] = exp2f(S1[j][0] - m11);
                    S1[j][1] = exp2f(S1[j][1] - m11);
                    S1[j][2] = exp2f(S1[j][2] - m12);
                    S1[j][3] = exp2f(S1[j][3] - m12);
                    rs1 += S1[j][0] + S1[j][1];
                    rs2 += S1[j][2] + S1[j][3];
                }
                rs1 += __shfl_xor_sync(FULL, rs1, 1);
                rs1 += __shfl_xor_sync(FULL, rs1, 2);
                rs2 += __shfl_xor_sync(FULL, rs2, 1);
                rs2 += __shfl_xor_sync(FULL, rs2, 2);
                l11 = l11 * fi1 + rs1;
                l12 = l12 * fi2 + rs2;
#pragma unroll
                for (int j = 0; j < 8; j++) {
                    O1[j][0] *= fi1; O1[j][1] *= fi1;
                    O1[j][2] *= fi2; O1[j][3] *= fi2;
                }
            }

            // ---- shuffle transpose: S -> P A-frags (both blocks) ----
            uint32_t pa0[8][4], pa1[8][4];
#pragma unroll
            for (int j = 0; j < 8; j++) {
                {
                    float t0 = f2tff(S0[j][0]), t1 = f2tff(S0[j][1]);
                    float t2 = f2tff(S0[j][2]), t3 = f2tff(S0[j][3]);
                    float a0v0 = __shfl_sync(FULL, t0, src0);
                    float a0v1 = __shfl_sync(FULL, t1, src0);
                    float a1v0 = __shfl_sync(FULL, t2, src0);
                    float a1v1 = __shfl_sync(FULL, t3, src0);
                    float a2v0 = __shfl_sync(FULL, t0, src2);
                    float a2v1 = __shfl_sync(FULL, t1, src2);
                    float a3v0 = __shfl_sync(FULL, t2, src2);
                    float a3v1 = __shfl_sync(FULL, t3, src2);
                    pa0[j][0] = __float_as_uint(oddl ? a0v1 : a0v0);
                    pa0[j][1] = __float_as_uint(oddl ? a1v1 : a1v0);
                    pa0[j][2] = __float_as_uint(oddl ? a2v1 : a2v0);
                    pa0[j][3] = __float_as_uint(oddl ? a3v1 : a3v0);
                }
                {
                    float t0 = f2tff(S1[j][0]), t1 = f2tff(S1[j][1]);
                    float t2 = f2tff(S1[j][2]), t3 = f2tff(S1[j][3]);
                    float a0v0 = __shfl_sync(FULL, t0, src0);
                    float a0v1 = __shfl_sync(FULL, t1, src0);
                    float a1v0 = __shfl_sync(FULL, t2, src0);
                    float a1v1 = __shfl_sync(FULL, t3, src0);
                    float a2v0 = __shfl_sync(FULL, t0, src2);
                    float a2v1 = __shfl_sync(FULL, t1, src2);
                    float a3v0 = __shfl_sync(FULL, t2, src2);
                    float a3v1 = __shfl_sync(FULL, t3, src2);
                    pa1[j][0] = __float_as_uint(oddl ? a0v1 : a0v0);
                    pa1[j][1] = __float_as_uint(oddl ? a1v1 : a1v0);
                    pa1[j][2] = __float_as_uint(oddl ? a2v1 : a2v0);
                    pa1[j][3] = __float_as_uint(oddl ? a3v1 : a3v0);
                }
            }

            // ---- O += P @ V (both m-blocks share each V fragment) ----
#pragma unroll
            for (int j = 0; j < 8; j++)
#pragma unroll
                for (int kb = 0; kb < 8; kb++) {
                    float2 bv = *(const float2*)&Vb[(j * 8 + kb) * 64 + l * 2];
                    uint32_t bf[2] = {__float_as_uint(bv.x), __float_as_uint(bv.y)};
                    MMA_TF32(O0[j], pa0[kb], bf);
                    MMA_TF32(O1[j], pa1[kb], bf);
                }
        }

        stage = (stage == 2) ? 0 : stage + 1;
    }
#undef AISSUE

    // ---- epilogue ----
    const int b = bh >> 4, h = bh & 15;
    const float i01 = 1.f / l01, i02 = 1.f / l02;
    const float i11 = 1.f / l11, i12 = 1.f / l12;
    const int mgA = b * SS + qr1;
    const int mgB = b * SS + qr2;
    const int mgC = b * SS + qr3;
    const int mgD = b * SS + qr4;
#pragma unroll
    for (int j = 0; j < 8; j++) {
        int c0 = j * 8 + (l & 3) * 2;
        int k = h * HD + c0;
        store_ya_frag(mgA, k,     O0[j][0] * i01);
        store_ya_frag(mgA, k + 1, O0[j][1] * i01);
        store_ya_frag(mgB, k,     O0[j][2] * i02);
        store_ya_frag(mgB, k + 1, O0[j][3] * i02);
        store_ya_frag(mgC, k,     O1[j][0] * i11);
        store_ya_frag(mgC, k + 1, O1[j][1] * i11);
        store_ya_frag(mgD, k,     O1[j][2] * i12);
        store_ya_frag(mgD, k + 1, O1[j][3] * i12);
    }
}

// ---------------------------------------------------------------------------

extern "C" void kernel_launch(void* const* d_in, const int* in_sizes, int n_in,
                              void* d_out, int out_size) {
    const float* x      = (const float*)d_in[0];
    const float* w_attn = (const float*)d_in[1];
    const float* b_attn = (const float*)d_in[2];
    const float* w_proj = (const float*)d_in[3];
    const float* b_proj = (const float*)d_in[4];
    float* out = (float*)d_out;

    float* xa; cudaGetSymbolAddress((void**)&xa, g_xa);
    float* ya; cudaGetSymbolAddress((void**)&ya, g_ya);
    float* wa; cudaGetSymbolAddress((void**)&wa, g_wa);
    float* wp; cudaGetSymbolAddress((void**)&wp, g_wp);

    cudaFuncSetAttribute(gemm_cp<N_QKV, true>,
                         cudaFuncAttributeMaxDynamicSharedMemorySize, GEMM_SMEM);
    cudaFuncSetAttribute(gemm_cp<DD, false>,
                         cudaFuncAttributeMaxDynamicSharedMemorySize, GEMM_SMEM);
    cudaFuncSetAttribute(attn_mma2,
                         cudaFuncAttributeMaxDynamicSharedMemorySize, ATT2_SMEM);

    // 0) preconvert x + both weights in ONE launch
    conv_all<<<12288, 256>>>(x, w_attn, w_proj, xa, wa, wp);

    // 1) QKV projection -> frag buffers
    gemm_cp<N_QKV, true><<<dim3(N_QKV / 128, MROWS / 128), 256, GEMM_SMEM>>>(
        xa, wa, b_attn, nullptr);

    // 2) causal flash attention (R12 + exp2) -> A-frag of y
    attn_mma2<<<dim3(SS / 128, BB * HH), 128, ATT2_SMEM>>>();

    // 3) output projection
    gemm_cp<DD, false><<<dim3(DD / 128, MROWS / 128), 256, GEMM_SMEM>>>(
        ya, wp, b_proj, out);
}

// round 15
// speedup vs baseline: 1.2888x; 1.0002x over previous
#include <cuda_runtime.h>
#include <cstdint>

#define BB 2
#define SS 2048
#define DD 1024
#define HH 16
#define HD 64
#define MROWS (BB*SS)   // 4096
#define N_QKV (3*DD)    // 3072
#define KDIM 1024
#define NCHUNK (KDIM/32)

// ---------------- device scratch (no allocation allowed) -------------------
__device__ __align__(128) float g_xa[MROWS/128 * NCHUNK * 4096];  // A-frag of x
__device__ __align__(128) float g_ya[MROWS/128 * NCHUNK * 4096];  // A-frag of attn out
__device__ __align__(128) float g_wa[N_QKV/128 * NCHUNK * 4096];  // B-frag of w_attn
__device__ __align__(128) float g_wp[DD/128   * NCHUNK * 4096];   // B-frag of w_proj
__device__ __align__(128) float g_qf[32 * 131072];  // A-frag Q [bh][mb128][kb8][128]
__device__ __align__(128) float g_kf[32 * 131072];  // B-frag K [bh][sb256][kb8][64]
__device__ __align__(128) float g_vf[32 * 131072];  // B-frag V [bh][kt32][nb8][kb8][64]

__device__ __forceinline__ uint32_t f2tf(float x) {
    uint32_t r;
    asm("cvt.rna.tf32.f32 %0, %1;" : "=r"(r) : "f"(x));
    return r;
}
__device__ __forceinline__ float f2tff(float x) { return __uint_as_float(f2tf(x)); }

__device__ __forceinline__ uint32_t smem_u32(const void* p) {
    uint32_t a;
    asm("{ .reg .u64 t; cvta.to.shared.u64 t, %1; cvt.u32.u64 %0, t; }" : "=r"(a) : "l"(p));
    return a;
}

#define MMA_TF32(d, a, b) \
    asm volatile("mma.sync.aligned.m16n8k8.row.col.f32.tf32.tf32.f32 " \
        "{%0,%1,%2,%3}, {%4,%5,%6,%7}, {%8,%9}, {%0,%1,%2,%3};" \
        : "+f"((d)[0]), "+f"((d)[1]), "+f"((d)[2]), "+f"((d)[3]) \
        : "r"((a)[0]), "r"((a)[1]), "r"((a)[2]), "r"((a)[3]), \
          "r"((b)[0]), "r"((b)[1]))

#define CP16(dst, src) \
    asm volatile("cp.async.cg.shared.global [%0], [%1], 16;" :: "r"(dst), "l"(src) : "memory")
#define CP_COMMIT() asm volatile("cp.async.commit_group;" ::: "memory")
#define CP_WAIT1()  asm volatile("cp.async.wait_group 1;" ::: "memory")

// ---------------------------------------------------------------------------
// Direct fragment-layout scatter helpers (tf32 bits)
// ---------------------------------------------------------------------------
__device__ __forceinline__ void store_qkv_frag(int m, int n, float val) {
    const int b = m >> 11, s = m & 2047;
    const int which = n >> 10, h = (n >> 6) & 15, d = n & 63;
    const int bh = (b << 4) | h;
    const float tv = f2tff(val);
    if (which == 0) {
        int off = bh * 131072 + (s >> 4) * 1024 + (d >> 3) * 128
                + (((s & 7) << 2) | (d & 3)) * 4
                + ((s & 8) ? 1 : 0) + ((d & 4) ? 2 : 0);
        g_qf[off] = tv;
    } else if (which == 1) {
        int off = bh * 131072 + (s >> 3) * 512 + (d >> 3) * 64
                + (((s & 7) << 2) | (d & 3)) * 2 + ((d & 4) ? 1 : 0);
        g_kf[off] = tv;
    } else {
        int off = bh * 131072 + (s >> 6) * 4096 + (d >> 3) * 512 + ((s & 63) >> 3) * 64
                + (((d & 7) << 2) | (s & 3)) * 2 + ((s & 4) ? 1 : 0);
        g_vf[off] = tv;
    }
}

__device__ __forceinline__ void store_ya_frag(int m, int k, float val) {
    int off = (m >> 7) * 131072 + (k >> 5) * 4096 + ((m >> 4) & 7) * 512
            + ((k >> 3) & 3) * 128 + (((m & 7) << 2) | (k & 3)) * 4
            + ((m & 8) ? 1 : 0) + ((k & 4) ? 2 : 0);
    g_ya[off] = f2tff(val);
}

// ---------------------------------------------------------------------------
// Fused pre-conversion (one launch, block-range dispatch)
// ---------------------------------------------------------------------------
__global__ __launch_bounds__(256) void conv_all(const float* __restrict__ X,
                                                const float* __restrict__ Wa,
                                                const float* __restrict__ Wp,
                                                float* __restrict__ xa,
                                                float* __restrict__ wa,
                                                float* __restrict__ wp) {
    int blk = blockIdx.x;
    if (blk < 4096) {
        int idx = blk * 256 + threadIdx.x;
        int lane = idx & 31;
        int kb = (idx >> 5) & 3;
        int mb = (idx >> 7) & 7;
        int chunk = (idx >> 10) & 31;
        int mtile = idx >> 15;
        int r = lane >> 2, c = lane & 3;
        int m = mtile * 128 + mb * 16;
        int k = chunk * 32 + kb * 8;
        float4 v;
        v.x = f2tff(X[(size_t)(m + r) * KDIM + k + c]);
        v.y = f2tff(X[(size_t)(m + r + 8) * KDIM + k + c]);
        v.z = f2tff(X[(size_t)(m + r) * KDIM + k + c + 4]);
        v.w = f2tff(X[(size_t)(m + r + 8) * KDIM + k + c + 4]);
        *(float4*)(xa + (size_t)idx * 4) = v;
    } else if (blk < 10240) {
        const int N = N_QKV;
        int idx = (blk - 4096) * 256 + threadIdx.x;
        int lane = idx & 31;
        int kb = (idx >> 5) & 3;
        int nb = (idx >> 7) & 15;
        int chunk = (idx >> 11) & 31;
        int ntile = idx >> 16;
        int n = ntile * 128 + nb * 8 + (lane >> 2);
        int k = chunk * 32 + kb * 8 + (lane & 3);
        float2 v;
        v.x = f2tff(Wa[(size_t)k * N + n]);
        v.y = f2tff(Wa[(size_t)(k + 4) * N + n]);
        *(float2*)(wa + (size_t)idx * 2) = v;
    } else {
        const int N = DD;
        int idx = (blk - 10240) * 256 + threadIdx.x;
        int lane = idx & 31;
        int kb = (idx >> 5) & 3;
        int nb = (idx >> 7) & 15;
        int chunk = (idx >> 11) & 31;
        int ntile = idx >> 16;
        int n = ntile * 128 + nb * 8 + (lane >> 2);
        int k = chunk * 32 + kb * 8 + (lane & 3);
        float2 v;
        v.x = f2tff(Wp[(size_t)k * N + n]);
        v.y = f2tff(Wp[(size_t)(k + 4) * N + n]);
        *(float2*)(wp + (size_t)idx * 2) = v;
    }
}

// ---------------------------------------------------------------------------
// GEMM (R8/R11 config, unchanged)
// ---------------------------------------------------------------------------
#define GEMM_SMEM (3 * 32768)

template<int N, bool QKV>
__global__ __launch_bounds__(256, 2) void gemm_cp(const float* __restrict__ Afrag,
                                                  const float* __restrict__ Bfrag,
                                                  const float* __restrict__ bias,
                                                  float* __restrict__ Cout) {
    extern __shared__ float sm[];
    const uint32_t sb = smem_u32(sm);
    const int t = threadIdx.x;
    const int wid = t >> 5, lane = t & 31;
    const int warp_m = wid & 3, warp_n = wid >> 2;
    const int m0 = blockIdx.y * 128;
    const int n0 = blockIdx.x * 128;

    const float* Atile = Afrag + (size_t)blockIdx.y * (NCHUNK * 4096);
    const float* Btile = Bfrag + (size_t)blockIdx.x * (NCHUNK * 4096);

    float acc[2][8][4];
#pragma unroll
    for (int i = 0; i < 2; i++)
#pragma unroll
        for (int j = 0; j < 8; j++)
#pragma unroll
            for (int r = 0; r < 4; r++) acc[i][j][r] = 0.f;

#define ISSUE(c, s) do { \
        const float4* As_ = (const float4*)(Atile + (size_t)(c) * 4096) + t; \
        const float4* Bs_ = (const float4*)(Btile + (size_t)(c) * 4096) + t; \
        uint32_t d_ = sb + (uint32_t)(s) * 32768u + (uint32_t)t * 16u; \
        _Pragma("unroll") \
        for (int q = 0; q < 4; q++) CP16(d_ + q * 4096u, As_ + q * 256); \
        _Pragma("unroll") \
        for (int q = 0; q < 4; q++) CP16(d_ + 16384u + q * 4096u, Bs_ + q * 256); \
    } while (0)

    ISSUE(0, 0); CP_COMMIT();
    ISSUE(1, 1); CP_COMMIT();

    int stage = 0;
    int istage = 2;
#pragma unroll 1
    for (int c = 0; c < NCHUNK; c++) {
        CP_WAIT1();
        __syncthreads();

        const float* Ab = sm + stage * 8192;
        const float* Bb = Ab + 4096;
#pragma unroll
        for (int kb = 0; kb < 4; kb++) {
            uint32_t af[2][4], bf[8][2];
#pragma unroll
            for (int i = 0; i < 2; i++) {
                float4 v = *(const float4*)(Ab + ((warp_m * 2 + i) * 4 + kb) * 128 + lane * 4);
                af[i][0] = __float_as_uint(v.x); af[i][1] = __float_as_uint(v.y);
                af[i][2] = __float_as_uint(v.z); af[i][3] = __float_as_uint(v.w);
            }
#pragma unroll
            for (int j = 0; j < 8; j++) {
                float2 v = *(const float2*)(Bb + ((warp_n * 8 + j) * 4 + kb) * 64 + lane * 2);
                bf[j][0] = __float_as_uint(v.x); bf[j][1] = __float_as_uint(v.y);
            }
#pragma unroll
            for (int i = 0; i < 2; i++)
#pragma unroll
                for (int j = 0; j < 8; j++)
                    MMA_TF32(acc[i][j], af[i], bf[j]);
        }
        if (c + 2 < NCHUNK) ISSUE(c + 2, istage);
        CP_COMMIT();
        stage = (stage == 2) ? 0 : stage + 1;
        istage = (istage == 2) ? 0 : istage + 1;
    }
#undef ISSUE

    const int r0 = lane >> 2;
    const int cp = (lane & 3) * 2;
#pragma unroll
    for (int i = 0; i < 2; i++) {
        const int mbase = m0 + warp_m * 32 + i * 16;
        const int m1 = mbase + r0;
        const int m2 = m1 + 8;
#pragma unroll
        for (int j = 0; j < 8; j++) {
            const int n = n0 + warp_n * 64 + j * 8 + cp;
            const float bx = bias[n], by = bias[n + 1];
            if (QKV) {
                store_qkv_frag(m1, n,     acc[i][j][0] + bx);
                store_qkv_frag(m1, n + 1, acc[i][j][1] + by);
                store_qkv_frag(m2, n,     acc[i][j][2] + bx);
                store_qkv_frag(m2, n + 1, acc[i][j][3] + by);
            } else {
                *(float2*)(Cout + (size_t)m1 * DD + n) =
                    make_float2(acc[i][j][0] + bx, acc[i][j][1] + by);
                *(float2*)(Cout + (size_t)m2 * DD + n) =
                    make_float2(acc[i][j][2] + bx, acc[i][j][3] + by);
            }
        }
    }
}

// ---------------------------------------------------------------------------
// Flash attention v6: split kt loop into full tiles [0,2qt) (branch-free body)
// and 2 boundary tiles [2qt,2qt+2) (masked body). Numerics identical to R14.
// 128 threads (4 warps x 32 q-rows); 3-buffer cp.async; shuffle P transpose.
// ---------------------------------------------------------------------------
#define ATT2_SMEM (3 * 32768)
#define SCL2 0.1803368801111244f   // 0.125 * log2(e)

__global__ __launch_bounds__(128, 2) void attn_mma2() {
    extern __shared__ float sh[];
    const uint32_t sbase = smem_u32(sh);
    const int t = threadIdx.x;
    const int w = t >> 5, l = t & 31;
    const int qt = gridDim.x - 1 - blockIdx.x;   // heavy tiles first
    const int bh = blockIdx.y;

    const float* Qf  = g_qf + (size_t)bh * 131072 + (size_t)(qt * 8 + w * 2) * 1024;
    const float* Kbh = g_kf + (size_t)bh * 131072;
    const float* Vbh = g_vf + (size_t)bh * 131072;

    uint32_t qa0[8][4], qa1[8][4];
#pragma unroll
    for (int kb = 0; kb < 8; kb++) {
        float4 v0 = *(const float4*)(Qf + kb * 128 + l * 4);
        float4 v1 = *(const float4*)(Qf + 1024 + kb * 128 + l * 4);
        qa0[kb][0] = __float_as_uint(v0.x); qa0[kb][1] = __float_as_uint(v0.y);
        qa0[kb][2] = __float_as_uint(v0.z); qa0[kb][3] = __float_as_uint(v0.w);
        qa1[kb][0] = __float_as_uint(v1.x); qa1[kb][1] = __float_as_uint(v1.y);
        qa1[kb][2] = __float_as_uint(v1.z); qa1[kb][3] = __float_as_uint(v1.w);
    }

    float O0[8][4], O1[8][4];
#pragma unroll
    for (int j = 0; j < 8; j++)
#pragma unroll
        for (int r = 0; r < 4; r++) { O0[j][r] = 0.f; O1[j][r] = 0.f; }
    float m01 = -1e30f, m02 = -1e30f, l01 = 0.f, l02 = 0.f;
    float m11 = -1e30f, m12 = -1e30f, l11 = 0.f, l12 = 0.f;

    const int ntiles = 2 * qt + 2;
    const int nfull  = 2 * qt;        // tiles [0,nfull) are unmasked for ALL warps
    const int qrow_lo = qt * 128 + w * 32;
    const int qr1 = qrow_lo + (l >> 2);
    const int qr2 = qr1 + 8;
    const int qr3 = qr1 + 16;
    const int qr4 = qr1 + 24;

    const unsigned FULL = 0xffffffffu;
    const int sgrp = l & 0x1c;
    const int src0 = sgrp + ((l & 3) >> 1);
    const int src2 = src0 + 2;
    const bool oddl = (l & 1);

#define AISSUE(kt) do { \
        if ((kt) < ntiles) { \
            const float4* ks_ = (const float4*)(Kbh + (size_t)(kt) * 4096) + t; \
            const float4* vs_ = (const float4*)(Vbh + (size_t)(kt) * 4096) + t; \
            uint32_t db_ = sbase + (uint32_t)((kt) % 3) * 32768u + (uint32_t)t * 16u; \
            _Pragma("unroll") \
            for (int q = 0; q < 8; q++) CP16(db_ + q * 2048u, ks_ + q * 128); \
            _Pragma("unroll") \
            for (int q = 0; q < 8; q++) CP16(db_ + 16384u + q * 2048u, vs_ + q * 128); \
        } } while (0)

// S = Q@K^T for both m-blocks (shared K fragments)
#define DO_S(Kb) do { \
    _Pragma("unroll") \
    for (int j = 0; j < 8; j++) { \
        _Pragma("unroll") \
        for (int r = 0; r < 4; r++) { S0[j][r] = 0.f; S1[j][r] = 0.f; } \
        _Pragma("unroll") \
        for (int kb = 0; kb < 8; kb++) { \
            float2 bv = *(const float2*)&(Kb)[(j * 8 + kb) * 64 + l * 2]; \
            uint32_t bf[2] = {__float_as_uint(bv.x), __float_as_uint(bv.y)}; \
            MMA_TF32(S0[j], qa0[kb], bf); \
            MMA_TF32(S1[j], qa1[kb], bf); \
        } \
    } } while (0)

// online softmax for one block (S, m-hi pair, l pair, O)
#define DO_SOFTMAX(S, mA, mB, lA, lB, O) do { \
    float rm1 = -1e30f, rm2 = -1e30f; \
    _Pragma("unroll") \
    for (int j = 0; j < 8; j++) { \
        rm1 = fmaxf(rm1, fmaxf((S)[j][0], (S)[j][1])); \
        rm2 = fmaxf(rm2, fmaxf((S)[j][2], (S)[j][3])); \
    } \
    rm1 = fmaxf(rm1, __shfl_xor_sync(FULL, rm1, 1)); \
    rm1 = fmaxf(rm1, __shfl_xor_sync(FULL, rm1, 2)); \
    rm2 = fmaxf(rm2, __shfl_xor_sync(FULL, rm2, 1)); \
    rm2 = fmaxf(rm2, __shfl_xor_sync(FULL, rm2, 2)); \
    float mn1 = fmaxf(mA, rm1), mn2 = fmaxf(mB, rm2); \
    float fi1 = exp2f(mA - mn1), fi2 = exp2f(mB - mn2); \
    mA = mn1; mB = mn2; \
    float rs1 = 0.f, rs2 = 0.f; \
    _Pragma("unroll") \
    for (int j = 0; j < 8; j++) { \
        (S)[j][0] = exp2f((S)[j][0] - mA); \
        (S)[j][1] = exp2f((S)[j][1] - mA); \
        (S)[j][2] = exp2f((S)[j][2] - mB); \
        (S)[j][3] = exp2f((S)[j][3] - mB); \
        rs1 += (S)[j][0] + (S)[j][1]; \
        rs2 += (S)[j][2] + (S)[j][3]; \
    } \
    rs1 += __shfl_xor_sync(FULL, rs1, 1); \
    rs1 += __shfl_xor_sync(FULL, rs1, 2); \
    rs2 += __shfl_xor_sync(FULL, rs2, 1); \
    rs2 += __shfl_xor_sync(FULL, rs2, 2); \
    lA = lA * fi1 + rs1; \
    lB = lB * fi2 + rs2; \
    _Pragma("unroll") \
    for (int j = 0; j < 8; j++) { \
        (O)[j][0] *= fi1; (O)[j][1] *= fi1; \
        (O)[j][2] *= fi2; (O)[j][3] *= fi2; \
    } } while (0)

#define TRANSPOSE_P(Sarr, paarr) do { \
    _Pragma("unroll") \
    for (int j = 0; j < 8; j++) { \
        float t0 = f2tff((Sarr)[j][0]), t1 = f2tff((Sarr)[j][1]); \
        float t2 = f2tff((Sarr)[j][2]), t3 = f2tff((Sarr)[j][3]); \
        float a0v0 = __shfl_sync(FULL, t0, src0); \
        float a0v1 = __shfl_sync(FULL, t1, src0); \
        float a1v0 = __shfl_sync(FULL, t2, src0); \
        float a1v1 = __shfl_sync(FULL, t3, src0); \
        float a2v0 = __shfl_sync(FULL, t0, src2); \
        float a2v1 = __shfl_sync(FULL, t1, src2); \
        float a3v0 = __shfl_sync(FULL, t2, src2); \
        float a3v1 = __shfl_sync(FULL, t3, src2); \
        (paarr)[j][0] = __float_as_uint(oddl ? a0v1 : a0v0); \
        (paarr)[j][1] = __float_as_uint(oddl ? a1v1 : a1v0); \
        (paarr)[j][2] = __float_as_uint(oddl ? a2v1 : a2v0); \
        (paarr)[j][3] = __float_as_uint(oddl ? a3v1 : a3v0); \
    } } while (0)

#define DO_PV(Vb) do { \
    _Pragma("unroll") \
    for (int j = 0; j < 8; j++) \
        _Pragma("unroll") \
        for (int kb = 0; kb < 8; kb++) { \
            float2 bv = *(const float2*)&(Vb)[(j * 8 + kb) * 64 + l * 2]; \
            uint32_t bf[2] = {__float_as_uint(bv.x), __float_as_uint(bv.y)}; \
            MMA_TF32(O0[j], pa0[kb], bf); \
            MMA_TF32(O1[j], pa1[kb], bf); \
        } } while (0)

    AISSUE(0); CP_COMMIT();
    AISSUE(1); CP_COMMIT();

    // ============== full tiles: branch-free body =================
#pragma unroll 1
    for (int kt = 0; kt < nfull; kt++) {
        CP_WAIT1();
        __syncthreads();
        AISSUE(kt + 2);
        CP_COMMIT();

        const float* Kb = sh + (kt % 3) * 8192;
        const float* Vb = Kb + 4096;

        float S0[8][4], S1[8][4];
        DO_S(Kb);
#pragma unroll
        for (int j = 0; j < 8; j++)
#pragma unroll
            for (int r = 0; r < 4; r++) { S0[j][r] *= SCL2; S1[j][r] *= SCL2; }

        DO_SOFTMAX(S0, m01, m02, l01, l02, O0);
        DO_SOFTMAX(S1, m11, m12, l11, l12, O1);

        uint32_t pa0[8][4], pa1[8][4];
        TRANSPOSE_P(S0, pa0);
        TRANSPOSE_P(S1, pa1);
        DO_PV(Vb);
    }

    // ============== boundary tiles (masked) ======================
#pragma unroll 1
    for (int kt = nfull; kt < ntiles; kt++) {
        CP_WAIT1();
        __syncthreads();
        AISSUE(kt + 2);
        CP_COMMIT();

        const bool active = (kt * 64) <= (qrow_lo + 31);
        if (active) {
            const float* Kb = sh + (kt % 3) * 8192;
            const float* Vb = Kb + 4096;

            float S0[8][4], S1[8][4];
            DO_S(Kb);

            if (kt * 64 + 63 > qrow_lo) {
#pragma unroll
                for (int j = 0; j < 8; j++) {
                    int c0 = kt * 64 + j * 8 + (l & 3) * 2, c1 = c0 + 1;
                    S0[j][0] = (c0 <= qr1) ? S0[j][0] * SCL2 : -1e30f;
                    S0[j][1] = (c1 <= qr1) ? S0[j][1] * SCL2 : -1e30f;
                    S0[j][2] = (c0 <= qr2) ? S0[j][2] * SCL2 : -1e30f;
                    S0[j][3] = (c1 <= qr2) ? S0[j][3] * SCL2 : -1e30f;
                    S1[j][0] = (c0 <= qr3) ? S1[j][0] * SCL2 : -1e30f;
                    S1[j][1] = (c1 <= qr3) ? S1[j][1] * SCL2 : -1e30f;
                    S1[j][2] = (c0 <= qr4) ? S1[j][2] * SCL2 : -1e30f;
                    S1[j][3] = (c1 <= qr4) ? S1[j][3] * SCL2 : -1e30f;
                }
            } else {
#pragma unroll
                for (int j = 0; j < 8; j++)
#pragma unroll
                    for (int r = 0; r < 4; r++) { S0[j][r] *= SCL2; S1[j][r] *= SCL2; }
            }

            DO_SOFTMAX(S0, m01, m02, l01, l02, O0);
            DO_SOFTMAX(S1, m11, m12, l11, l12, O1);

            uint32_t pa0[8][4], pa1[8][4];
            TRANSPOSE_P(S0, pa0);
            TRANSPOSE_P(S1, pa1);
            DO_PV(Vb);
        }
    }
#undef AISSUE
#undef DO_S
#undef DO_SOFTMAX
#undef TRANSPOSE_P
#undef DO_PV

    // ---- epilogue ----
    const int b = bh >> 4, h = bh & 15;
    const float i01 = 1.f / l01, i02 = 1.f / l02;
    const float i11 = 1.f / l11, i12 = 1.f / l12;
    const int mgA = b * SS + qr1;
    const int mgB = b * SS + qr2;
    const int mgC = b * SS + qr3;
    const int mgD = b * SS + qr4;
#pragma unroll
    for (int j = 0; j < 8; j++) {
        int c0 = j * 8 + (l & 3) * 2;
        int k = h * HD + c0;
        store_ya_frag(mgA, k,     O0[j][0] * i01);
        store_ya_frag(mgA, k + 1, O0[j][1] * i01);
        store_ya_frag(mgB, k,     O0[j][2] * i02);
        store_ya_frag(mgB, k + 1, O0[j][3] * i02);
        store_ya_frag(mgC, k,     O1[j][0] * i11);
        store_ya_frag(mgC, k + 1, O1[j][1] * i11);
        store_ya_frag(mgD, k,     O1[j][2] * i12);
        store_ya_frag(mgD, k + 1, O1[j][3] * i12);
    }
}

// ---------------------------------------------------------------------------

extern "C" void kernel_launch(void* const* d_in, const int* in_sizes, int n_in,
                              void* d_out, int out_size) {
    const float* x      = (const float*)d_in[0];
    const float* w_attn = (const float*)d_in[1];
    const float* b_attn = (const float*)d_in[2];
    const float* w_proj = (const float*)d_in[3];
    const float* b_proj = (const float*)d_in[4];
    float* out = (float*)d_out;

    float* xa; cudaGetSymbolAddress((void**)&xa, g_xa);
    float* ya; cudaGetSymbolAddress((void**)&ya, g_ya);
    float* wa; cudaGetSymbolAddress((void**)&wa, g_wa);
    float* wp; cudaGetSymbolAddress((void**)&wp, g_wp);

    cudaFuncSetAttribute(gemm_cp<N_QKV, true>,
                         cudaFuncAttributeMaxDynamicSharedMemorySize, GEMM_SMEM);
    cudaFuncSetAttribute(gemm_cp<DD, false>,
                         cudaFuncAttributeMaxDynamicSharedMemorySize, GEMM_SMEM);
    cudaFuncSetAttribute(attn_mma2,
                         cudaFuncAttributeMaxDynamicSharedMemorySize, ATT2_SMEM);

    // 0) preconvert x + both weights in ONE launch
    conv_all<<<12288, 256>>>(x, w_attn, w_proj, xa, wa, wp);

    // 1) QKV projection -> frag buffers
    gemm_cp<N_QKV, true><<<dim3(N_QKV / 128, MROWS / 128), 256, GEMM_SMEM>>>(
        xa, wa, b_attn, nullptr);

    // 2) causal flash attention (v6: split full/boundary loops) -> A-frag of y
    attn_mma2<<<dim3(SS / 128, BB * HH), 128, ATT2_SMEM>>>();

    // 3) output projection
    gemm_cp<DD, false><<<dim3(DD / 128, MROWS / 128), 256, GEMM_SMEM>>>(
        ya, wp, b_proj, out);
}

// round 16
// speedup vs baseline: 1.2919x; 1.0024x over previous
#include <cuda_runtime.h>
#include <cstdint>

#define BB 2
#define SS 2048
#define DD 1024
#define HH 16
#define HD 64
#define MROWS (BB*SS)   // 4096
#define N_QKV (3*DD)    // 3072
#define KDIM 1024
#define NCHUNK (KDIM/32)

// ---------------- device scratch (no allocation allowed) -------------------
__device__ __align__(128) float g_xa[MROWS/128 * NCHUNK * 4096];  // A-frag of x
__device__ __align__(128) float g_ya[MROWS/128 * NCHUNK * 4096];  // A-frag of attn out
__device__ __align__(128) float g_wa[N_QKV/128 * NCHUNK * 4096];  // B-frag of w_attn
__device__ __align__(128) float g_wp[DD/128   * NCHUNK * 4096];   // B-frag of w_proj
__device__ __align__(128) float g_qf[32 * 131072];  // A-frag Q [bh][mb128][kb8][128]
__device__ __align__(128) float g_kf[32 * 131072];  // B-frag K [bh][sb256][kb8][64]
__device__ __align__(128) float g_vf[32 * 131072];  // B-frag V [bh][kt32][nb8][kb8][64]

__device__ __forceinline__ uint32_t f2tf(float x) {
    uint32_t r;
    asm("cvt.rna.tf32.f32 %0, %1;" : "=r"(r) : "f"(x));
    return r;
}
__device__ __forceinline__ float f2tff(float x) { return __uint_as_float(f2tf(x)); }

__device__ __forceinline__ uint32_t smem_u32(const void* p) {
    uint32_t a;
    asm("{ .reg .u64 t; cvta.to.shared.u64 t, %1; cvt.u32.u64 %0, t; }" : "=r"(a) : "l"(p));
    return a;
}

#define MMA_TF32(d, a, b) \
    asm volatile("mma.sync.aligned.m16n8k8.row.col.f32.tf32.tf32.f32 " \
        "{%0,%1,%2,%3}, {%4,%5,%6,%7}, {%8,%9}, {%0,%1,%2,%3};" \
        : "+f"((d)[0]), "+f"((d)[1]), "+f"((d)[2]), "+f"((d)[3]) \
        : "r"((a)[0]), "r"((a)[1]), "r"((a)[2]), "r"((a)[3]), \
          "r"((b)[0]), "r"((b)[1]))

#define CP16(dst, src) \
    asm volatile("cp.async.cg.shared.global [%0], [%1], 16;" :: "r"(dst), "l"(src) : "memory")
#define CP_COMMIT() asm volatile("cp.async.commit_group;" ::: "memory")
#define CP_WAIT1()  asm volatile("cp.async.wait_group 1;" ::: "memory")

// ---------------------------------------------------------------------------
// Direct fragment-layout scatter helpers (tf32 bits)
// ---------------------------------------------------------------------------
__device__ __forceinline__ void store_qkv_frag(int m, int n, float val) {
    const int b = m >> 11, s = m & 2047;
    const int which = n >> 10, h = (n >> 6) & 15, d = n & 63;
    const int bh = (b << 4) | h;
    const float tv = f2tff(val);
    if (which == 0) {
        int off = bh * 131072 + (s >> 4) * 1024 + (d >> 3) * 128
                + (((s & 7) << 2) | (d & 3)) * 4
                + ((s & 8) ? 1 : 0) + ((d & 4) ? 2 : 0);
        g_qf[off] = tv;
    } else if (which == 1) {
        int off = bh * 131072 + (s >> 3) * 512 + (d >> 3) * 64
                + (((s & 7) << 2) | (d & 3)) * 2 + ((d & 4) ? 1 : 0);
        g_kf[off] = tv;
    } else {
        int off = bh * 131072 + (s >> 6) * 4096 + (d >> 3) * 512 + ((s & 63) >> 3) * 64
                + (((d & 7) << 2) | (s & 3)) * 2 + ((s & 4) ? 1 : 0);
        g_vf[off] = tv;
    }
}

__device__ __forceinline__ void store_ya_frag(int m, int k, float val) {
    int off = (m >> 7) * 131072 + (k >> 5) * 4096 + ((m >> 4) & 7) * 512
            + ((k >> 3) & 3) * 128 + (((m & 7) << 2) | (k & 3)) * 4
            + ((m & 8) ? 1 : 0) + ((k & 4) ? 2 : 0);
    g_ya[off] = f2tff(val);
}

// ---------------------------------------------------------------------------
// Fused pre-conversion (one launch, block-range dispatch)
// ---------------------------------------------------------------------------
__global__ __launch_bounds__(256) void conv_all(const float* __restrict__ X,
                                                const float* __restrict__ Wa,
                                                const float* __restrict__ Wp,
                                                float* __restrict__ xa,
                                                float* __restrict__ wa,
                                                float* __restrict__ wp) {
    int blk = blockIdx.x;
    if (blk < 4096) {
        int idx = blk * 256 + threadIdx.x;
        int lane = idx & 31;
        int kb = (idx >> 5) & 3;
        int mb = (idx >> 7) & 7;
        int chunk = (idx >> 10) & 31;
        int mtile = idx >> 15;
        int r = lane >> 2, c = lane & 3;
        int m = mtile * 128 + mb * 16;
        int k = chunk * 32 + kb * 8;
        float4 v;
        v.x = f2tff(X[(size_t)(m + r) * KDIM + k + c]);
        v.y = f2tff(X[(size_t)(m + r + 8) * KDIM + k + c]);
        v.z = f2tff(X[(size_t)(m + r) * KDIM + k + c + 4]);
        v.w = f2tff(X[(size_t)(m + r + 8) * KDIM + k + c + 4]);
        *(float4*)(xa + (size_t)idx * 4) = v;
    } else if (blk < 10240) {
        const int N = N_QKV;
        int idx = (blk - 4096) * 256 + threadIdx.x;
        int lane = idx & 31;
        int kb = (idx >> 5) & 3;
        int nb = (idx >> 7) & 15;
        int chunk = (idx >> 11) & 31;
        int ntile = idx >> 16;
        int n = ntile * 128 + nb * 8 + (lane >> 2);
        int k = chunk * 32 + kb * 8 + (lane & 3);
        float2 v;
        v.x = f2tff(Wa[(size_t)k * N + n]);
        v.y = f2tff(Wa[(size_t)(k + 4) * N + n]);
        *(float2*)(wa + (size_t)idx * 2) = v;
    } else {
        const int N = DD;
        int idx = (blk - 10240) * 256 + threadIdx.x;
        int lane = idx & 31;
        int kb = (idx >> 5) & 3;
        int nb = (idx >> 7) & 15;
        int chunk = (idx >> 11) & 31;
        int ntile = idx >> 16;
        int n = ntile * 128 + nb * 8 + (lane >> 2);
        int k = chunk * 32 + kb * 8 + (lane & 3);
        float2 v;
        v.x = f2tff(Wp[(size_t)k * N + n]);
        v.y = f2tff(Wp[(size_t)(k + 4) * N + n]);
        *(float2*)(wp + (size_t)idx * 2) = v;
    }
}

// ---------------------------------------------------------------------------
// QKV GEMM v2: CTA 128m x 64n, 8 warps (4m x 2n), warp tile 32x32.
// Registers ~80 -> 3 CTAs/SM (24 warps/SM). 3-stage 24KB stages (72KB smem).
// ---------------------------------------------------------------------------
#define QKV_SMEM (3 * 24576)

__global__ __launch_bounds__(256, 3) void qkv_gemm64(const float* __restrict__ Afrag,
                                                     const float* __restrict__ Bfrag,
                                                     const float* __restrict__ bias) {
    extern __shared__ float sm[];
    const uint32_t sb = smem_u32(sm);
    const int t = threadIdx.x;
    const int wid = t >> 5, lane = t & 31;
    const int warp_m = wid & 3;     // 4 warps along M (32 rows each)
    const int warp_n = wid >> 2;    // 2 warps along N (32 cols each)
    const int m0 = blockIdx.y * 128;
    const int n0 = blockIdx.x * 64;

    const float* Atile = Afrag + (size_t)blockIdx.y * (NCHUNK * 4096);
    // B slice: 64 of the 128 cols of ntile (blockIdx.x>>1); nb-major layout
    const float* Btile = Bfrag + (size_t)(blockIdx.x >> 1) * (NCHUNK * 4096)
                               + (blockIdx.x & 1) * 2048;

    float acc[2][4][4];
#pragma unroll
    for (int i = 0; i < 2; i++)
#pragma unroll
        for (int j = 0; j < 4; j++)
#pragma unroll
            for (int r = 0; r < 4; r++) acc[i][j][r] = 0.f;

#define QISSUE(c, s) do { \
        const float4* As_ = (const float4*)(Atile + (size_t)(c) * 4096) + t; \
        const float4* Bs_ = (const float4*)(Btile + (size_t)(c) * 4096) + t * 2; \
        uint32_t da_ = sb + (uint32_t)(s) * 24576u + (uint32_t)t * 16u; \
        uint32_t db_ = sb + (uint32_t)(s) * 24576u + 16384u + (uint32_t)t * 32u; \
        _Pragma("unroll") \
        for (int q = 0; q < 4; q++) CP16(da_ + q * 4096u, As_ + q * 256); \
        _Pragma("unroll") \
        for (int q = 0; q < 2; q++) CP16(db_ + q * 16u, Bs_ + q); \
    } while (0)

    QISSUE(0, 0); CP_COMMIT();
    QISSUE(1, 1); CP_COMMIT();

    int stage = 0;
    int istage = 2;
#pragma unroll 1
    for (int c = 0; c < NCHUNK; c++) {
        CP_WAIT1();
        __syncthreads();

        const float* Ab = sm + stage * 6144;
        const float* Bw = Ab + 4096 + warp_n * 1024;
#pragma unroll
        for (int kb = 0; kb < 4; kb++) {
            uint32_t af[2][4], bf[4][2];
#pragma unroll
            for (int i = 0; i < 2; i++) {
                float4 v = *(const float4*)(Ab + ((warp_m * 2 + i) * 4 + kb) * 128 + lane * 4);
                af[i][0] = __float_as_uint(v.x); af[i][1] = __float_as_uint(v.y);
                af[i][2] = __float_as_uint(v.z); af[i][3] = __float_as_uint(v.w);
            }
#pragma unroll
            for (int j = 0; j < 4; j++) {
                float2 v = *(const float2*)(Bw + (j * 4 + kb) * 64 + lane * 2);
                bf[j][0] = __float_as_uint(v.x); bf[j][1] = __float_as_uint(v.y);
            }
#pragma unroll
            for (int i = 0; i < 2; i++)
#pragma unroll
                for (int j = 0; j < 4; j++)
                    MMA_TF32(acc[i][j], af[i], bf[j]);
        }
        if (c + 2 < NCHUNK) QISSUE(c + 2, istage);
        CP_COMMIT();
        stage = (stage == 2) ? 0 : stage + 1;
        istage = (istage == 2) ? 0 : istage + 1;
    }
#undef QISSUE

    // Epilogue -> Q/K/V frag buffers
    const int r0 = lane >> 2;
    const int cp = (lane & 3) * 2;
#pragma unroll
    for (int i = 0; i < 2; i++) {
        const int mbase = m0 + warp_m * 32 + i * 16;
        const int m1 = mbase + r0;
        const int m2 = m1 + 8;
#pragma unroll
        for (int j = 0; j < 4; j++) {
            const int n = n0 + warp_n * 32 + j * 8 + cp;
            const float bx = bias[n], by = bias[n + 1];
            store_qkv_frag(m1, n,     acc[i][j][0] + bx);
            store_qkv_frag(m1, n + 1, acc[i][j][1] + by);
            store_qkv_frag(m2, n,     acc[i][j][2] + bx);
            store_qkv_frag(m2, n + 1, acc[i][j][3] + by);
        }
    }
}

// ---------------------------------------------------------------------------
// Proj GEMM (R8/R11 config, unchanged): CTA 128x128, 8 warps, 3-stage.
// ---------------------------------------------------------------------------
#define GEMM_SMEM (3 * 32768)

__global__ __launch_bounds__(256, 2) void proj_gemm(const float* __restrict__ Afrag,
                                                    const float* __restrict__ Bfrag,
                                                    const float* __restrict__ bias,
                                                    float* __restrict__ Cout) {
    extern __shared__ float sm[];
    const uint32_t sb = smem_u32(sm);
    const int t = threadIdx.x;
    const int wid = t >> 5, lane = t & 31;
    const int warp_m = wid & 3, warp_n = wid >> 2;
    const int m0 = blockIdx.y * 128;
    const int n0 = blockIdx.x * 128;

    const float* Atile = Afrag + (size_t)blockIdx.y * (NCHUNK * 4096);
    const float* Btile = Bfrag + (size_t)blockIdx.x * (NCHUNK * 4096);

    float acc[2][8][4];
#pragma unroll
    for (int i = 0; i < 2; i++)
#pragma unroll
        for (int j = 0; j < 8; j++)
#pragma unroll
            for (int r = 0; r < 4; r++) acc[i][j][r] = 0.f;

#define ISSUE(c, s) do { \
        const float4* As_ = (const float4*)(Atile + (size_t)(c) * 4096) + t; \
        const float4* Bs_ = (const float4*)(Btile + (size_t)(c) * 4096) + t; \
        uint32_t d_ = sb + (uint32_t)(s) * 32768u + (uint32_t)t * 16u; \
        _Pragma("unroll") \
        for (int q = 0; q < 4; q++) CP16(d_ + q * 4096u, As_ + q * 256); \
        _Pragma("unroll") \
        for (int q = 0; q < 4; q++) CP16(d_ + 16384u + q * 4096u, Bs_ + q * 256); \
    } while (0)

    ISSUE(0, 0); CP_COMMIT();
    ISSUE(1, 1); CP_COMMIT();

    int stage = 0;
    int istage = 2;
#pragma unroll 1
    for (int c = 0; c < NCHUNK; c++) {
        CP_WAIT1();
        __syncthreads();

        const float* Ab = sm + stage * 8192;
        const float* Bb = Ab + 4096;
#pragma unroll
        for (int kb = 0; kb < 4; kb++) {
            uint32_t af[2][4], bf[8][2];
#pragma unroll
            for (int i = 0; i < 2; i++) {
                float4 v = *(const float4*)(Ab + ((warp_m * 2 + i) * 4 + kb) * 128 + lane * 4);
                af[i][0] = __float_as_uint(v.x); af[i][1] = __float_as_uint(v.y);
                af[i][2] = __float_as_uint(v.z); af[i][3] = __float_as_uint(v.w);
            }
#pragma unroll
            for (int j = 0; j < 8; j++) {
                float2 v = *(const float2*)(Bb + ((warp_n * 8 + j) * 4 + kb) * 64 + lane * 2);
                bf[j][0] = __float_as_uint(v.x); bf[j][1] = __float_as_uint(v.y);
            }
#pragma unroll
            for (int i = 0; i < 2; i++)
#pragma unroll
                for (int j = 0; j < 8; j++)
                    MMA_TF32(acc[i][j], af[i], bf[j]);
        }
        if (c + 2 < NCHUNK) ISSUE(c + 2, istage);
        CP_COMMIT();
        stage = (stage == 2) ? 0 : stage + 1;
        istage = (istage == 2) ? 0 : istage + 1;
    }
#undef ISSUE

    const int r0 = lane >> 2;
    const int cp = (lane & 3) * 2;
#pragma unroll
    for (int i = 0; i < 2; i++) {
        const int mbase = m0 + warp_m * 32 + i * 16;
        const int m1 = mbase + r0;
        const int m2 = m1 + 8;
#pragma unroll
        for (int j = 0; j < 8; j++) {
            const int n = n0 + warp_n * 64 + j * 8 + cp;
            const float bx = bias[n], by = bias[n + 1];
            *(float2*)(Cout + (size_t)m1 * DD + n) =
                make_float2(acc[i][j][0] + bx, acc[i][j][1] + by);
            *(float2*)(Cout + (size_t)m2 * DD + n) =
                make_float2(acc[i][j][2] + bx, acc[i][j][3] + by);
        }
    }
}

// ---------------------------------------------------------------------------
// Flash attention (R15, unchanged): split full/boundary loops, exp2, 4 warps
// x 32 q-rows, 3-buffer cp.async, shuffle P transpose.
// ---------------------------------------------------------------------------
#define ATT2_SMEM (3 * 32768)
#define SCL2 0.1803368801111244f   // 0.125 * log2(e)

__global__ __launch_bounds__(128, 2) void attn_mma2() {
    extern __shared__ float sh[];
    const uint32_t sbase = smem_u32(sh);
    const int t = threadIdx.x;
    const int w = t >> 5, l = t & 31;
    const int qt = gridDim.x - 1 - blockIdx.x;   // heavy tiles first
    const int bh = blockIdx.y;

    const float* Qf  = g_qf + (size_t)bh * 131072 + (size_t)(qt * 8 + w * 2) * 1024;
    const float* Kbh = g_kf + (size_t)bh * 131072;
    const float* Vbh = g_vf + (size_t)bh * 131072;

    uint32_t qa0[8][4], qa1[8][4];
#pragma unroll
    for (int kb = 0; kb < 8; kb++) {
        float4 v0 = *(const float4*)(Qf + kb * 128 + l * 4);
        float4 v1 = *(const float4*)(Qf + 1024 + kb * 128 + l * 4);
        qa0[kb][0] = __float_as_uint(v0.x); qa0[kb][1] = __float_as_uint(v0.y);
        qa0[kb][2] = __float_as_uint(v0.z); qa0[kb][3] = __float_as_uint(v0.w);
        qa1[kb][0] = __float_as_uint(v1.x); qa1[kb][1] = __float_as_uint(v1.y);
        qa1[kb][2] = __float_as_uint(v1.z); qa1[kb][3] = __float_as_uint(v1.w);
    }

    float O0[8][4], O1[8][4];
#pragma unroll
    for (int j = 0; j < 8; j++)
#pragma unroll
        for (int r = 0; r < 4; r++) { O0[j][r] = 0.f; O1[j][r] = 0.f; }
    float m01 = -1e30f, m02 = -1e30f, l01 = 0.f, l02 = 0.f;
    float m11 = -1e30f, m12 = -1e30f, l11 = 0.f, l12 = 0.f;

    const int ntiles = 2 * qt + 2;
    const int nfull  = 2 * qt;
    const int qrow_lo = qt * 128 + w * 32;
    const int qr1 = qrow_lo + (l >> 2);
    const int qr2 = qr1 + 8;
    const int qr3 = qr1 + 16;
    const int qr4 = qr1 + 24;

    const unsigned FULL = 0xffffffffu;
    const int sgrp = l & 0x1c;
    const int src0 = sgrp + ((l & 3) >> 1);
    const int src2 = src0 + 2;
    const bool oddl = (l & 1);

#define AISSUE(kt) do { \
        if ((kt) < ntiles) { \
            const float4* ks_ = (const float4*)(Kbh + (size_t)(kt) * 4096) + t; \
            const float4* vs_ = (const float4*)(Vbh + (size_t)(kt) * 4096) + t; \
            uint32_t db_ = sbase + (uint32_t)((kt) % 3) * 32768u + (uint32_t)t * 16u; \
            _Pragma("unroll") \
            for (int q = 0; q < 8; q++) CP16(db_ + q * 2048u, ks_ + q * 128); \
            _Pragma("unroll") \
            for (int q = 0; q < 8; q++) CP16(db_ + 16384u + q * 2048u, vs_ + q * 128); \
        } } while (0)

#define DO_S(Kb) do { \
    _Pragma("unroll") \
    for (int j = 0; j < 8; j++) { \
        _Pragma("unroll") \
        for (int r = 0; r < 4; r++) { S0[j][r] = 0.f; S1[j][r] = 0.f; } \
        _Pragma("unroll") \
        for (int kb = 0; kb < 8; kb++) { \
            float2 bv = *(const float2*)&(Kb)[(j * 8 + kb) * 64 + l * 2]; \
            uint32_t bf[2] = {__float_as_uint(bv.x), __float_as_uint(bv.y)}; \
            MMA_TF32(S0[j], qa0[kb], bf); \
            MMA_TF32(S1[j], qa1[kb], bf); \
        } \
    } } while (0)

#define DO_SOFTMAX(S, mA, mB, lA, lB, O) do { \
    float rm1 = -1e30f, rm2 = -1e30f; \
    _Pragma("unroll") \
    for (int j = 0; j < 8; j++) { \
        rm1 = fmaxf(rm1, fmaxf((S)[j][0], (S)[j][1])); \
        rm2 = fmaxf(rm2, fmaxf((S)[j][2], (S)[j][3])); \
    } \
    rm1 = fmaxf(rm1, __shfl_xor_sync(FULL, rm1, 1)); \
    rm1 = fmaxf(rm1, __shfl_xor_sync(FULL, rm1, 2)); \
    rm2 = fmaxf(rm2, __shfl_xor_sync(FULL, rm2, 1)); \
    rm2 = fmaxf(rm2, __shfl_xor_sync(FULL, rm2, 2)); \
    float mn1 = fmaxf(mA, rm1), mn2 = fmaxf(mB, rm2); \
    float fi1 = exp2f(mA - mn1), fi2 = exp2f(mB - mn2); \
    mA = mn1; mB = mn2; \
    float rs1 = 0.f, rs2 = 0.f; \
    _Pragma("unroll") \
    for (int j = 0; j < 8; j++) { \
        (S)[j][0] = exp2f((S)[j][0] - mA); \
        (S)[j][1] = exp2f((S)[j][1] - mA); \
        (S)[j][2] = exp2f((S)[j][2] - mB); \
        (S)[j][3] = exp2f((S)[j][3] - mB); \
        rs1 += (S)[j][0] + (S)[j][1]; \
        rs2 += (S)[j][2] + (S)[j][3]; \
    } \
    rs1 += __shfl_xor_sync(FULL, rs1, 1); \
    rs1 += __shfl_xor_sync(FULL, rs1, 2); \
    rs2 += __shfl_xor_sync(FULL, rs2, 1); \
    rs2 += __shfl_xor_sync(FULL, rs2, 2); \
    lA = lA * fi1 + rs1; \
    lB = lB * fi2 + rs2; \
    _Pragma("unroll") \
    for (int j = 0; j < 8; j++) { \
        (O)[j][0] *= fi1; (O)[j][1] *= fi1; \
        (O)[j][2] *= fi2; (O)[j][3] *= fi2; \
    } } while (0)

#define TRANSPOSE_P(Sarr, paarr) do { \
    _Pragma("unroll") \
    for (int j = 0; j < 8; j++) { \
        float t0 = f2tff((Sarr)[j][0]), t1 = f2tff((Sarr)[j][1]); \
        float t2 = f2tff((Sarr)[j][2]), t3 = f2tff((Sarr)[j][3]); \
        float a0v0 = __shfl_sync(FULL, t0, src0); \
        float a0v1 = __shfl_sync(FULL, t1, src0); \
        float a1v0 = __shfl_sync(FULL, t2, src0); \
        float a1v1 = __shfl_sync(FULL, t3, src0); \
        float a2v0 = __shfl_sync(FULL, t0, src2); \
        float a2v1 = __shfl_sync(FULL, t1, src2); \
        float a3v0 = __shfl_sync(FULL, t2, src2); \
        float a3v1 = __shfl_sync(FULL, t3, src2); \
        (paarr)[j][0] = __float_as_uint(oddl ? a0v1 : a0v0); \
        (paarr)[j][1] = __float_as_uint(oddl ? a1v1 : a1v0); \
        (paarr)[j][2] = __float_as_uint(oddl ? a2v1 : a2v0); \
        (paarr)[j][3] = __float_as_uint(oddl ? a3v1 : a3v0); \
    } } while (0)

#define DO_PV(Vb) do { \
    _Pragma("unroll") \
    for (int j = 0; j < 8; j++) \
        _Pragma("unroll") \
        for (int kb = 0; kb < 8; kb++) { \
            float2 bv = *(const float2*)&(Vb)[(j * 8 + kb) * 64 + l * 2]; \
            uint32_t bf[2] = {__float_as_uint(bv.x), __float_as_uint(bv.y)}; \
            MMA_TF32(O0[j], pa0[kb], bf); \
            MMA_TF32(O1[j], pa1[kb], bf); \
        } } while (0)

    AISSUE(0); CP_COMMIT();
    AISSUE(1); CP_COMMIT();

#pragma unroll 1
    for (int kt = 0; kt < nfull; kt++) {
        CP_WAIT1();
        __syncthreads();
        AISSUE(kt + 2);
        CP_COMMIT();

        const float* Kb = sh + (kt % 3) * 8192;
        const float* Vb = Kb + 4096;

        float S0[8][4], S1[8][4];
        DO_S(Kb);
#pragma unroll
        for (int j = 0; j < 8; j++)
#pragma unroll
            for (int r = 0; r < 4; r++) { S0[j][r] *= SCL2; S1[j][r] *= SCL2; }

        DO_SOFTMAX(S0, m01, m02, l01, l02, O0);
        DO_SOFTMAX(S1, m11, m12, l11, l12, O1);

        uint32_t pa0[8][4], pa1[8][4];
        TRANSPOSE_P(S0, pa0);
        TRANSPOSE_P(S1, pa1);
        DO_PV(Vb);
    }

#pragma unroll 1
    for (int kt = nfull; kt < ntiles; kt++) {
        CP_WAIT1();
        __syncthreads();
        AISSUE(kt + 2);
        CP_COMMIT();

        const bool active = (kt * 64) <= (qrow_lo + 31);
        if (active) {
            const float* Kb = sh + (kt % 3) * 8192;
            const float* Vb = Kb + 4096;

            float S0[8][4], S1[8][4];
            DO_S(Kb);

            if (kt * 64 + 63 > qrow_lo) {
#pragma unroll
                for (int j = 0; j < 8; j++) {
                    int c0 = kt * 64 + j * 8 + (l & 3) * 2, c1 = c0 + 1;
                    S0[j][0] = (c0 <= qr1) ? S0[j][0] * SCL2 : -1e30f;
                    S0[j][1] = (c1 <= qr1) ? S0[j][1] * SCL2 : -1e30f;
                    S0[j][2] = (c0 <= qr2) ? S0[j][2] * SCL2 : -1e30f;
                    S0[j][3] = (c1 <= qr2) ? S0[j][3] * SCL2 : -1e30f;
                    S1[j][0] = (c0 <= qr3) ? S1[j][0] * SCL2 : -1e30f;
                    S1[j][1] = (c1 <= qr3) ? S1[j][1] * SCL2 : -1e30f;
                    S1[j][2] = (c0 <= qr4) ? S1[j][2] * SCL2 : -1e30f;
                    S1[j][3] = (c1 <= qr4) ? S1[j][3] * SCL2 : -1e30f;
                }
            } else {
#pragma unroll
                for (int j = 0; j < 8; j++)
#pragma unroll
                    for (int r = 0; r < 4; r++) { S0[j][r] *= SCL2; S1[j][r] *= SCL2; }
            }

            DO_SOFTMAX(S0, m01, m02, l01, l02, O0);
            DO_SOFTMAX(S1, m11, m12, l11, l12, O1);

            uint32_t pa0[8][4], pa1[8][4];
            TRANSPOSE_P(S0, pa0);
            TRANSPOSE_P(S1, pa1);
            DO_PV(Vb);
        }
    }
#undef AISSUE
#undef DO_S
#undef DO_SOFTMAX
#undef TRANSPOSE_P
#undef DO_PV

    const int b = bh >> 4, h = bh & 15;
    const float i01 = 1.f / l01, i02 = 1.f / l02;
    const float i11 = 1.f / l11, i12 = 1.f / l12;
    const int mgA = b * SS + qr1;
    const int mgB = b * SS + qr2;
    const int mgC = b * SS + qr3;
    const int mgD = b * SS + qr4;
#pragma unroll
    for (int j = 0; j < 8; j++) {
        int c0 = j * 8 + (l & 3) * 2;
        int k = h * HD + c0;
        store_ya_frag(mgA, k,     O0[j][0] * i01);
        store_ya_frag(mgA, k + 1, O0[j][1] * i01);
        store_ya_frag(mgB, k,     O0[j][2] * i02);
        store_ya_frag(mgB, k + 1, O0[j][3] * i02);
        store_ya_frag(mgC, k,     O1[j][0] * i11);
        store_ya_frag(mgC, k + 1, O1[j][1] * i11);
        store_ya_frag(mgD, k,     O1[j][2] * i12);
        store_ya_frag(mgD, k + 1, O1[j][3] * i12);
    }
}

// ---------------------------------------------------------------------------

extern "C" void kernel_launch(void* const* d_in, const int* in_sizes, int n_in,
                              void* d_out, int out_size) {
    const float* x      = (const float*)d_in[0];
    const float* w_attn = (const float*)d_in[1];
    const float* b_attn = (const float*)d_in[2];
    const float* w_proj = (const float*)d_in[3];
    const float* b_proj = (const float*)d_in[4];
    float* out = (float*)d_out;

    float* xa; cudaGetSymbolAddress((void**)&xa, g_xa);
    float* ya; cudaGetSymbolAddress((void**)&ya, g_ya);
    float* wa; cudaGetSymbolAddress((void**)&wa, g_wa);
    float* wp; cudaGetSymbolAddress((void**)&wp, g_wp);

    cudaFuncSetAttribute(qkv_gemm64,
                         cudaFuncAttributeMaxDynamicSharedMemorySize, QKV_SMEM);
    cudaFuncSetAttribute(proj_gemm,
                         cudaFuncAttributeMaxDynamicSharedMemorySize, GEMM_SMEM);
    cudaFuncSetAttribute(attn_mma2,
                         cudaFuncAttributeMaxDynamicSharedMemorySize, ATT2_SMEM);

    // 0) preconvert x + both weights in ONE launch
    conv_all<<<12288, 256>>>(x, w_attn, w_proj, xa, wa, wp);

    // 1) QKV projection -> frag buffers (128x64 CTAs, 3 CTAs/SM)
    qkv_gemm64<<<dim3(N_QKV / 64, MROWS / 128), 256, QKV_SMEM>>>(xa, wa, b_attn);

    // 2) causal flash attention -> A-frag of y
    attn_mma2<<<dim3(SS / 128, BB * HH), 128, ATT2_SMEM>>>();

    // 3) output projection
    proj_gemm<<<dim3(DD / 128, MROWS / 128), 256, GEMM_SMEM>>>(
        ya, wp, b_proj, out);
}